// round 14
// baseline (speedup 1.0000x reference)
#include <cuda_runtime.h>
#include <cuda_bf16.h>
#include <mma.h>
#include <cstdint>

using namespace nvcuda;

#define L 256
#define D 128
#define H 4
#define SCALING 0.17677669529663687f

// ---- scratch ----
__device__ __align__(16) float g_q[L * L * D];
__device__ __align__(16) float g_k[L * L * D];
__device__ __align__(16) float g_v[L * L * D];
__device__ __align__(16) float g_gate[L * L * D];
__device__ __align__(16) float g_biasH[H * L * L];            // [h][j][k]
__device__ __align__(16) __nv_bfloat16 g_y_hi[L * L * D];     // gate*att, bf16 hi
__device__ __align__(16) __nv_bfloat16 g_y_lo[L * L * D];     // bf16 lo
__device__ __align__(16) __nv_bfloat16 g_B_hi[128 * 512];     // [k][n] (Wq|Wk|Wv|Wg)
__device__ __align__(16) __nv_bfloat16 g_B_lo[128 * 512];
__device__ __align__(16) __nv_bfloat16 g_Wo_hi[128 * 128];    // [k][n]
__device__ __align__(16) __nv_bfloat16 g_Wo_lo[128 * 128];

__device__ __forceinline__ __nv_bfloat16 bhi(float x) { return __float2bfloat16_rn(x); }
__device__ __forceinline__ __nv_bfloat16 blo(float x, __nv_bfloat16 h) {
    return __float2bfloat16_rn(x - __bfloat162float(h));
}

// ---- prep ----
__global__ void __launch_bounds__(256) prep_kernel(
    const float* __restrict__ Wq, const float* __restrict__ Wk,
    const float* __restrict__ Wv, const float* __restrict__ Wg,
    const float* __restrict__ Wo)
{
    if (blockIdx.x < 256) {
        int idx = blockIdx.x * 256 + threadIdx.x;
        int k = idx >> 9;
        int n = idx & 511;
        const float* W = (n < 128) ? Wq : (n < 256) ? Wk : (n < 384) ? Wv : Wg;
        float w = W[k * 128 + (n & 127)];
        __nv_bfloat16 h = bhi(w);
        g_B_hi[idx] = h;
        g_B_lo[idx] = blo(w, h);
    } else {
        int idx = (blockIdx.x - 256) * 256 + threadIdx.x;
        float w = Wo[idx];
        __nv_bfloat16 h = bhi(w);
        g_Wo_hi[idx] = h;
        g_Wo_lo[idx] = blo(w, h);
    }
}

// ============================= proj (r10 exact) =============================
#define LDA 136
#define LDB2 72
#define A_HI_OFF 0
#define A_LO_OFF (128 * LDA * 2)
#define B_HI_OFF (2 * 128 * LDA * 2)              // 69632
#define B_LO_OFF (B_HI_OFF + 128 * LDB2 * 2)
#define PROJ_SMEM (B_LO_OFF + 128 * LDB2 * 2)     // 106496
#define STAGE_OFF B_HI_OFF                         // fp32 [128][68]

__global__ void __launch_bounds__(256, 2) proj_wmma_kernel(
    const float* __restrict__ pair,
    const float* __restrict__ gamma, const float* __restrict__ beta,
    const float* __restrict__ Wb, const float* __restrict__ bg)
{
    extern __shared__ char smem[];
    __nv_bfloat16* sAhi = reinterpret_cast<__nv_bfloat16*>(smem + A_HI_OFF);
    __nv_bfloat16* sAlo = reinterpret_cast<__nv_bfloat16*>(smem + A_LO_OFF);
    __nv_bfloat16* sBhi = reinterpret_cast<__nv_bfloat16*>(smem + B_HI_OFF);
    __nv_bfloat16* sBlo = reinterpret_cast<__nv_bfloat16*>(smem + B_LO_OFF);
    float* stage = reinterpret_cast<float*>(smem + STAGE_OFF);

    const int t = threadIdx.x;
    const int wid = t >> 5, lane = t & 31;
    const int row0 = blockIdx.x * 128;

    float4 gv = reinterpret_cast<const float4*>(gamma)[lane];
    float4 bv = reinterpret_cast<const float4*>(beta)[lane];
    float4 wbr[4];
#pragma unroll
    for (int i = 0; i < 4; ++i)
        wbr[i] = *reinterpret_cast<const float4*>(Wb + (lane * 4 + i) * 4);

#pragma unroll 2
    for (int rr = 0; rr < 16; ++rr) {
        int r = wid * 16 + rr;
        float4 x = reinterpret_cast<const float4*>(pair + (size_t)(row0 + r) * D)[lane];
        float s  = x.x + x.y + x.z + x.w;
        float s2 = x.x * x.x + x.y * x.y + x.z * x.z + x.w * x.w;
#pragma unroll
        for (int o = 16; o > 0; o >>= 1) {
            s  += __shfl_xor_sync(0xffffffffu, s,  o);
            s2 += __shfl_xor_sync(0xffffffffu, s2, o);
        }
        float mu  = s * (1.0f / 128.0f);
        float var = s2 * (1.0f / 128.0f) - mu * mu;
        float rs  = rsqrtf(var + 1e-5f);
        float4 xn;
        xn.x = (x.x - mu) * rs * gv.x + bv.x;
        xn.y = (x.y - mu) * rs * gv.y + bv.y;
        xn.z = (x.z - mu) * rs * gv.z + bv.z;
        xn.w = (x.w - mu) * rs * gv.w + bv.w;

        __nv_bfloat16 h0 = bhi(xn.x), h1 = bhi(xn.y), h2 = bhi(xn.z), h3 = bhi(xn.w);
        size_t aoff = (size_t)r * LDA + lane * 4;
        reinterpret_cast<__nv_bfloat162*>(sAhi + aoff)[0] = {h0, h1};
        reinterpret_cast<__nv_bfloat162*>(sAhi + aoff)[1] = {h2, h3};
        reinterpret_cast<__nv_bfloat162*>(sAlo + aoff)[0] = {blo(xn.x, h0), blo(xn.y, h1)};
        reinterpret_cast<__nv_bfloat162*>(sAlo + aoff)[1] = {blo(xn.z, h2), blo(xn.w, h3)};

        float4 bacc;
        bacc.x = xn.x * wbr[0].x + xn.y * wbr[1].x + xn.z * wbr[2].x + xn.w * wbr[3].x;
        bacc.y = xn.x * wbr[0].y + xn.y * wbr[1].y + xn.z * wbr[2].y + xn.w * wbr[3].y;
        bacc.z = xn.x * wbr[0].z + xn.y * wbr[1].z + xn.z * wbr[2].z + xn.w * wbr[3].z;
        bacc.w = xn.x * wbr[0].w + xn.y * wbr[1].w + xn.z * wbr[2].w + xn.w * wbr[3].w;
#pragma unroll
        for (int o = 16; o > 0; o >>= 1) {
            bacc.x += __shfl_xor_sync(0xffffffffu, bacc.x, o);
            bacc.y += __shfl_xor_sync(0xffffffffu, bacc.y, o);
            bacc.z += __shfl_xor_sync(0xffffffffu, bacc.z, o);
            bacc.w += __shfl_xor_sync(0xffffffffu, bacc.w, o);
        }
        if (lane == 0) {
            int p = row0 + r;
            g_biasH[0 * 65536 + p] = bacc.x;
            g_biasH[1 * 65536 + p] = bacc.y;
            g_biasH[2 * 65536 + p] = bacc.z;
            g_biasH[3 * 65536 + p] = bacc.w;
        }
    }

    const int wm = (wid & 3) * 32;
    const int wn = (wid >> 2) * 32;

    for (int c = 0; c < 8; ++c) {
        const bool three = (c >= 4);   // v and gate need the W_lo correction
        __syncthreads();               // prior chunk's B/stage reads done
#pragma unroll
        for (int it = 0; it < 4; ++it) {
            int idx = it * 256 + t;
            int k = idx >> 3, u = idx & 7;
            size_t src = (size_t)k * 512 + c * 64 + u * 8;
            size_t dst = (size_t)k * LDB2 + u * 8;
            *reinterpret_cast<uint4*>(sBhi + dst) = *reinterpret_cast<const uint4*>(g_B_hi + src);
            *reinterpret_cast<uint4*>(sBlo + dst) = *reinterpret_cast<const uint4*>(g_B_lo + src);
        }
        __syncthreads();

        wmma::fragment<wmma::accumulator, 16, 16, 16, float> acc[2][2];
#pragma unroll
        for (int i = 0; i < 2; ++i)
#pragma unroll
            for (int j = 0; j < 2; ++j) wmma::fill_fragment(acc[i][j], 0.0f);

#pragma unroll
        for (int k8 = 0; k8 < 8; ++k8) {
            wmma::fragment<wmma::matrix_a, 16, 16, 16, __nv_bfloat16, wmma::row_major> afh[2], afl[2];
            wmma::load_matrix_sync(afh[0], sAhi + (size_t)(wm +  0) * LDA + k8 * 16, LDA);
            wmma::load_matrix_sync(afh[1], sAhi + (size_t)(wm + 16) * LDA + k8 * 16, LDA);
            wmma::load_matrix_sync(afl[0], sAlo + (size_t)(wm +  0) * LDA + k8 * 16, LDA);
            wmma::load_matrix_sync(afl[1], sAlo + (size_t)(wm + 16) * LDA + k8 * 16, LDA);
#pragma unroll
            for (int j = 0; j < 2; ++j) {
                wmma::fragment<wmma::matrix_b, 16, 16, 16, __nv_bfloat16, wmma::row_major> bfh;
                wmma::load_matrix_sync(bfh, sBhi + (size_t)(k8 * 16) * LDB2 + wn + j * 16, LDB2);
                wmma::mma_sync(acc[0][j], afh[0], bfh, acc[0][j]);
                wmma::mma_sync(acc[1][j], afh[1], bfh, acc[1][j]);
                wmma::mma_sync(acc[0][j], afl[0], bfh, acc[0][j]);
                wmma::mma_sync(acc[1][j], afl[1], bfh, acc[1][j]);
                if (three) {
                    wmma::fragment<wmma::matrix_b, 16, 16, 16, __nv_bfloat16, wmma::row_major> bfl;
                    wmma::load_matrix_sync(bfl, sBlo + (size_t)(k8 * 16) * LDB2 + wn + j * 16, LDB2);
                    wmma::mma_sync(acc[0][j], afh[0], bfl, acc[0][j]);
                    wmma::mma_sync(acc[1][j], afh[1], bfl, acc[1][j]);
                }
            }
        }

        if (c < 6) {
            float* dst = (c < 2) ? g_q : (c < 4) ? g_k : g_v;
            int coloff = (c & 1) * 64;
            if (c < 2) {
#pragma unroll
                for (int i = 0; i < 2; ++i)
#pragma unroll
                    for (int j = 0; j < 2; ++j)
#pragma unroll
                        for (int e = 0; e < acc[i][j].num_elements; ++e)
                            acc[i][j].x[e] *= SCALING;
            }
#pragma unroll
            for (int i = 0; i < 2; ++i)
#pragma unroll
                for (int j = 0; j < 2; ++j)
                    wmma::store_matrix_sync(
                        dst + (size_t)(row0 + wm + i * 16) * D + coloff + wn + j * 16,
                        acc[i][j], D, wmma::mem_row_major);
        } else {
            int coloff = (c - 6) * 64;
            __syncthreads();
#pragma unroll
            for (int i = 0; i < 2; ++i)
#pragma unroll
                for (int j = 0; j < 2; ++j)
                    wmma::store_matrix_sync(
                        stage + (size_t)(wm + i * 16) * 68 + wn + j * 16,
                        acc[i][j], 68, wmma::mem_row_major);
            __syncthreads();
#pragma unroll
            for (int it = 0; it < 8; ++it) {
                int idx = it * 256 + t;
                int r = idx >> 4, q = idx & 15;
                float4 v = *reinterpret_cast<const float4*>(stage + (size_t)r * 68 + q * 4);
                float4 bgv = *reinterpret_cast<const float4*>(bg + coloff + q * 4);
                float4 o;
                o.x = 1.0f / (1.0f + __expf(-(v.x + bgv.x)));
                o.y = 1.0f / (1.0f + __expf(-(v.y + bgv.y)));
                o.z = 1.0f / (1.0f + __expf(-(v.z + bgv.z)));
                o.w = 1.0f / (1.0f + __expf(-(v.w + bgv.w)));
                *reinterpret_cast<float4*>(g_gate + (size_t)(row0 + r) * D + coloff + q * 4) = o;
            }
        }
    }
}

// ============================= attn =============================
// r10 + centered-P: out = sumV + P' V (P' = exp(s)-1, single bf16).
// PV passes 3 -> 2; Ptl buffer eliminated.
#define LDQ 40
#define LDSS 260
#define LDP2 264
#define LDO 36
#define AQH 0
#define AKB 20480
#define AVH 40960
#define AVL 61440
#define AST 81920
#define APH 98560
#define APV 107008                 // partials [8][32] f32 + sumV [32] f32
#define ATTN_SMEM 108288

__global__ void __launch_bounds__(256, 2) attn_wmma_kernel()
{
    extern __shared__ char smem[];
    __nv_bfloat16* Qh  = reinterpret_cast<__nv_bfloat16*>(smem + AQH);
    __nv_bfloat16* Kb  = reinterpret_cast<__nv_bfloat16*>(smem + AKB);
    __nv_bfloat16* Vh  = reinterpret_cast<__nv_bfloat16*>(smem + AVH);
    __nv_bfloat16* Vl  = reinterpret_cast<__nv_bfloat16*>(smem + AVL);
    float*         St  = reinterpret_cast<float*>(smem + AST);
    __nv_bfloat16* Pth = reinterpret_cast<__nv_bfloat16*>(smem + APH);
    float*     partial = reinterpret_cast<float*>(smem + APV);          // [8][32]
    float*        sumV = reinterpret_cast<float*>(smem + APV + 1024);   // [32]
    float*       Sout  = reinterpret_cast<float*>(smem + 0);

    const int i = blockIdx.x;
    const int h = blockIdx.y;
    const int t = threadIdx.x;
    const int w = t >> 5;
    const size_t gbase = (size_t)i * 256 * 128 + h * 32;

#pragma unroll
    for (int u = 0; u < 8; ++u) {
        int idx = u * 256 + t;
        int row = idx >> 3, c4 = idx & 7;
        size_t goff = gbase + (size_t)row * 128 + c4 * 4;
        size_t soff = (size_t)row * LDQ + c4 * 4;
        float4 q4 = *reinterpret_cast<const float4*>(g_q + goff);
        float4 k4 = *reinterpret_cast<const float4*>(g_k + goff);
        float4 v4 = *reinterpret_cast<const float4*>(g_v + goff);
        reinterpret_cast<__nv_bfloat162*>(Qh + soff)[0] = {bhi(q4.x), bhi(q4.y)};
        reinterpret_cast<__nv_bfloat162*>(Qh + soff)[1] = {bhi(q4.z), bhi(q4.w)};
        reinterpret_cast<__nv_bfloat162*>(Kb + soff)[0] = {bhi(k4.x), bhi(k4.y)};
        reinterpret_cast<__nv_bfloat162*>(Kb + soff)[1] = {bhi(k4.z), bhi(k4.w)};
        __nv_bfloat16 vh0 = bhi(v4.x), vh1 = bhi(v4.y), vh2 = bhi(v4.z), vh3 = bhi(v4.w);
        reinterpret_cast<__nv_bfloat162*>(Vh + soff)[0] = {vh0, vh1};
        reinterpret_cast<__nv_bfloat162*>(Vh + soff)[1] = {vh2, vh3};
        reinterpret_cast<__nv_bfloat162*>(Vl + soff)[0] = {blo(v4.x, vh0), blo(v4.y, vh1)};
        reinterpret_cast<__nv_bfloat162*>(Vl + soff)[1] = {blo(v4.z, vh2), blo(v4.w, vh3)};
    }

    // sumV partials: warp w sums k-rows [w*32, w*32+32) of column (lane)
    {
        int lane = t & 31;
        float acc = 0.0f;
        const float* vp = g_v + gbase + (size_t)(w * 32) * 128 + lane;
#pragma unroll 8
        for (int kk = 0; kk < 32; ++kk) acc += vp[(size_t)kk * 128];
        partial[w * 32 + lane] = acc;
    }
    __syncthreads();
    if (t < 32) {
        float s = 0.0f;
#pragma unroll
        for (int w2 = 0; w2 < 8; ++w2) s += partial[w2 * 32 + t];
        sumV[t] = s;
    }
    __syncthreads();

    const float* biasp = g_biasH + (size_t)h * 65536;
    const int j0w = w * 32;

    wmma::fragment<wmma::accumulator, 16, 16, 16, float> acc_o[2][2];
#pragma unroll
    for (int a = 0; a < 2; ++a)
#pragma unroll
        for (int b = 0; b < 2; ++b) wmma::fill_fragment(acc_o[a][b], 0.0f);
    float ssum = 0.0f;

    for (int c = 0; c < 16; ++c) {
        const int k0c = c * 16;

        // ---- S = bias + Qh K^T (warp-private St columns) ----
        wmma::fragment<wmma::accumulator, 16, 16, 16, float> accs[2];
#pragma unroll
        for (int a = 0; a < 2; ++a)
            wmma::load_matrix_sync(accs[a],
                biasp + (size_t)(j0w + a * 16) * 256 + k0c, 256, wmma::mem_row_major);
#pragma unroll
        for (int s = 0; s < 2; ++s) {
            wmma::fragment<wmma::matrix_b, 16, 16, 16, __nv_bfloat16, wmma::col_major> kf;
            wmma::load_matrix_sync(kf, Kb + (size_t)k0c * LDQ + s * 16, LDQ);
            wmma::fragment<wmma::matrix_a, 16, 16, 16, __nv_bfloat16, wmma::row_major> af[2];
            wmma::load_matrix_sync(af[0], Qh + (size_t)(j0w +  0) * LDQ + s * 16, LDQ);
            wmma::load_matrix_sync(af[1], Qh + (size_t)(j0w + 16) * LDQ + s * 16, LDQ);
            wmma::mma_sync(accs[0], af[0], kf, accs[0]);
            wmma::mma_sync(accs[1], af[1], kf, accs[1]);
        }
#pragma unroll
        for (int a = 0; a < 2; ++a)
            wmma::store_matrix_sync(St + j0w + a * 16, accs[a], LDSS, wmma::mem_col_major);
        __syncwarp();

        // ---- exp: thread t owns column j = t; store P' = p - 1 (bf16) ----
        {
            float acc = 0.0f;
#pragma unroll 4
            for (int kk = 0; kk < 16; ++kk) {
                float p = __expf(St[(size_t)kk * LDSS + t]);
                acc += p;
                Pth[(size_t)kk * LDP2 + t] = bhi(p - 1.0f);
            }
            ssum += acc;
        }
        __syncwarp();

        // ---- out += P' Vh + P' Vl ----
        wmma::fragment<wmma::matrix_a, 16, 16, 16, __nv_bfloat16, wmma::col_major> aph[2];
#pragma unroll
        for (int a = 0; a < 2; ++a)
            wmma::load_matrix_sync(aph[a], Pth + j0w + a * 16, LDP2);
#pragma unroll
        for (int b = 0; b < 2; ++b) {
            wmma::fragment<wmma::matrix_b, 16, 16, 16, __nv_bfloat16, wmma::row_major> vfh, vfl;
            wmma::load_matrix_sync(vfh, Vh + (size_t)k0c * LDQ + b * 16, LDQ);
            wmma::load_matrix_sync(vfl, Vl + (size_t)k0c * LDQ + b * 16, LDQ);
#pragma unroll
            for (int a = 0; a < 2; ++a) {
                wmma::mma_sync(acc_o[a][b], aph[a], vfh, acc_o[a][b]);
                wmma::mma_sync(acc_o[a][b], aph[a], vfl, acc_o[a][b]);
            }
        }
    }

    __syncthreads();   // all warps done reading Qh/Kb before Sout overwrites region 0
#pragma unroll
    for (int a = 0; a < 2; ++a)
#pragma unroll
        for (int b = 0; b < 2; ++b)
            wmma::store_matrix_sync(Sout + (size_t)(j0w + a * 16) * LDO + b * 16,
                                    acc_o[a][b], LDO, wmma::mem_row_major);
    __syncwarp();

    {
        float inv = 1.0f / ssum;
        const float* gp = g_gate + gbase + (size_t)t * 128;
        __nv_bfloat16* yh = g_y_hi + gbase + (size_t)t * 128;
        __nv_bfloat16* yl = g_y_lo + gbase + (size_t)t * 128;
#pragma unroll
        for (int d4 = 0; d4 < 8; ++d4) {
            float4 v = *reinterpret_cast<const float4*>(Sout + (size_t)t * LDO + d4 * 4);
            float4 sv = *reinterpret_cast<const float4*>(sumV + d4 * 4);
            float4 g = *reinterpret_cast<const float4*>(gp + d4 * 4);
            float4 y;
            y.x = (v.x + sv.x) * inv * g.x;
            y.y = (v.y + sv.y) * inv * g.y;
            y.z = (v.z + sv.z) * inv * g.z;
            y.w = (v.w + sv.w) * inv * g.w;
            __nv_bfloat16 h0 = bhi(y.x), h1 = bhi(y.y), h2 = bhi(y.z), h3 = bhi(y.w);
            reinterpret_cast<__nv_bfloat162*>(yh + d4 * 4)[0] = {h0, h1};
            reinterpret_cast<__nv_bfloat162*>(yh + d4 * 4)[1] = {h2, h3};
            reinterpret_cast<__nv_bfloat162*>(yl + d4 * 4)[0] = {blo(y.x, h0), blo(y.y, h1)};
            reinterpret_cast<__nv_bfloat162*>(yl + d4 * 4)[1] = {blo(y.z, h2), blo(y.w, h3)};
        }
    }
}

// ============================= epi (r10 exact) =============================
#define E_LDB 72
#define E_AHI 0
#define E_ALO (128 * 136 * 2)
#define E_BHI (2 * 128 * 136 * 2)                 // 69632
#define E_BLO (E_BHI + 128 * E_LDB * 2)
#define EPI_SMEM (E_BLO + 128 * E_LDB * 2)        // 106496
#define E_STAGE E_BHI

__global__ void __launch_bounds__(256, 2) epi_wmma_kernel(
    const float* __restrict__ bo, float* __restrict__ out)
{
    extern __shared__ char smem[];
    __nv_bfloat16* sAhi = reinterpret_cast<__nv_bfloat16*>(smem + E_AHI);
    __nv_bfloat16* sAlo = reinterpret_cast<__nv_bfloat16*>(smem + E_ALO);
    __nv_bfloat16* sBhi = reinterpret_cast<__nv_bfloat16*>(smem + E_BHI);
    __nv_bfloat16* sBlo = reinterpret_cast<__nv_bfloat16*>(smem + E_BLO);
    float* stage = reinterpret_cast<float*>(smem + E_STAGE);

    const int t = threadIdx.x;
    const int wid = t >> 5;
    const int row0 = blockIdx.x * 128;

#pragma unroll
    for (int it = 0; it < 8; ++it) {
        int idx = it * 256 + t;
        int r = idx >> 4, u = idx & 15;
        size_t src = (size_t)(row0 + r) * D + u * 8;
        size_t dst = (size_t)r * 136 + u * 8;
        *reinterpret_cast<uint4*>(sAhi + dst) = *reinterpret_cast<const uint4*>(g_y_hi + src);
        *reinterpret_cast<uint4*>(sAlo + dst) = *reinterpret_cast<const uint4*>(g_y_lo + src);
    }

    const int wm = (wid & 3) * 32;
    const int wn = (wid >> 2) * 32;

    for (int c = 0; c < 2; ++c) {
        __syncthreads();
#pragma unroll
        for (int it = 0; it < 4; ++it) {
            int idx = it * 256 + t;
            int k = idx >> 3, u = idx & 7;
            size_t src = (size_t)k * 128 + c * 64 + u * 8;
            size_t dst = (size_t)k * E_LDB + u * 8;
            *reinterpret_cast<uint4*>(sBhi + dst) = *reinterpret_cast<const uint4*>(g_Wo_hi + src);
            *reinterpret_cast<uint4*>(sBlo + dst) = *reinterpret_cast<const uint4*>(g_Wo_lo + src);
        }
        __syncthreads();

        wmma::fragment<wmma::accumulator, 16, 16, 16, float> acc[2][2];
#pragma unroll
        for (int i = 0; i < 2; ++i)
#pragma unroll
            for (int j = 0; j < 2; ++j) wmma::fill_fragment(acc[i][j], 0.0f);

#pragma unroll
        for (int k8 = 0; k8 < 8; ++k8) {
            wmma::fragment<wmma::matrix_a, 16, 16, 16, __nv_bfloat16, wmma::row_major> afh[2], afl[2];
            wmma::load_matrix_sync(afh[0], sAhi + (size_t)(wm +  0) * 136 + k8 * 16, 136);
            wmma::load_matrix_sync(afh[1], sAhi + (size_t)(wm + 16) * 136 + k8 * 16, 136);
            wmma::load_matrix_sync(afl[0], sAlo + (size_t)(wm +  0) * 136 + k8 * 16, 136);
            wmma::load_matrix_sync(afl[1], sAlo + (size_t)(wm + 16) * 136 + k8 * 16, 136);
#pragma unroll
            for (int j = 0; j < 2; ++j) {
                wmma::fragment<wmma::matrix_b, 16, 16, 16, __nv_bfloat16, wmma::row_major> bfh, bfl;
                wmma::load_matrix_sync(bfh, sBhi + (size_t)(k8 * 16) * E_LDB + wn + j * 16, E_LDB);
                wmma::load_matrix_sync(bfl, sBlo + (size_t)(k8 * 16) * E_LDB + wn + j * 16, E_LDB);
                wmma::mma_sync(acc[0][j], afh[0], bfh, acc[0][j]);
                wmma::mma_sync(acc[1][j], afh[1], bfh, acc[1][j]);
                wmma::mma_sync(acc[0][j], afl[0], bfh, acc[0][j]);
                wmma::mma_sync(acc[1][j], afl[1], bfh, acc[1][j]);
                wmma::mma_sync(acc[0][j], afh[0], bfl, acc[0][j]);
                wmma::mma_sync(acc[1][j], afh[1], bfl, acc[1][j]);
            }
        }

        __syncthreads();
#pragma unroll
        for (int i = 0; i < 2; ++i)
#pragma unroll
            for (int j = 0; j < 2; ++j)
                wmma::store_matrix_sync(stage + (size_t)(wm + i * 16) * 68 + wn + j * 16,
                                        acc[i][j], 68, wmma::mem_row_major);
        __syncthreads();

#pragma unroll
        for (int it = 0; it < 8; ++it) {
            int idx = it * 256 + t;
            int r = idx >> 4, q = idx & 15;
            float4 v = *reinterpret_cast<const float4*>(stage + (size_t)r * 68 + q * 4);
            float4 b = *reinterpret_cast<const float4*>(bo + c * 64 + q * 4);
            v.x += b.x; v.y += b.y; v.z += b.z; v.w += b.w;
            *reinterpret_cast<float4*>(out + (size_t)(row0 + r) * D + c * 64 + q * 4) = v;
        }
    }
}

extern "C" void kernel_launch(void* const* d_in, const int* in_sizes, int n_in,
                              void* d_out, int out_size)
{
    const float* pair  = (const float*)d_in[0];
    const float* gamma = (const float*)d_in[1];
    const float* beta  = (const float*)d_in[2];
    const float* Wq    = (const float*)d_in[3];
    const float* Wk    = (const float*)d_in[4];
    const float* Wv    = (const float*)d_in[5];
    const float* Wb    = (const float*)d_in[6];
    const float* Wg    = (const float*)d_in[7];
    const float* bg    = (const float*)d_in[8];
    const float* Wo    = (const float*)d_in[9];
    const float* bo    = (const float*)d_in[10];
    float* out = (float*)d_out;

    cudaFuncSetAttribute(proj_wmma_kernel, cudaFuncAttributeMaxDynamicSharedMemorySize, PROJ_SMEM);
    cudaFuncSetAttribute(attn_wmma_kernel, cudaFuncAttributeMaxDynamicSharedMemorySize, ATTN_SMEM);
    cudaFuncSetAttribute(epi_wmma_kernel,  cudaFuncAttributeMaxDynamicSharedMemorySize, EPI_SMEM);

    prep_kernel<<<320, 256>>>(Wq, Wk, Wv, Wg, Wo);
    proj_wmma_kernel<<<(L * L) / 128, 256, PROJ_SMEM>>>(pair, gamma, beta, Wb, bg);
    attn_wmma_kernel<<<dim3(L, H), 256, ATTN_SMEM>>>();
    epi_wmma_kernel<<<(L * L) / 128, 256, EPI_SMEM>>>(bo, out);
}

// round 15
// speedup vs baseline: 1.4264x; 1.4264x over previous
#include <cuda_runtime.h>
#include <cuda_bf16.h>
#include <mma.h>
#include <cstdint>

using namespace nvcuda;

#define L 256
#define D 128
#define H 4
#define SCALING 0.17677669529663687f

// ---- scratch ----
__device__ __align__(16) float g_q[L * L * D];
__device__ __align__(16) float g_k[L * L * D];
__device__ __align__(16) float g_v[L * L * D];
__device__ __align__(16) float g_gate[L * L * D];
__device__ __align__(16) float g_biasH[H * L * L];            // [h][j][k]
__device__ __align__(16) __nv_bfloat16 g_y_hi[L * L * D];     // gate*att, bf16 hi
__device__ __align__(16) __nv_bfloat16 g_y_lo[L * L * D];     // bf16 lo
__device__ __align__(16) __nv_bfloat16 g_B_hi[128 * 512];     // [k][n] (Wq|Wk|Wv|Wg)
__device__ __align__(16) __nv_bfloat16 g_B_lo[128 * 512];
__device__ __align__(16) __nv_bfloat16 g_Wo_hi[128 * 128];    // [k][n]
__device__ __align__(16) __nv_bfloat16 g_Wo_lo[128 * 128];

__device__ __forceinline__ __nv_bfloat16 bhi(float x) { return __float2bfloat16_rn(x); }
__device__ __forceinline__ __nv_bfloat16 blo(float x, __nv_bfloat16 h) {
    return __float2bfloat16_rn(x - __bfloat162float(h));
}

// ---- prep ----
__global__ void __launch_bounds__(256) prep_kernel(
    const float* __restrict__ Wq, const float* __restrict__ Wk,
    const float* __restrict__ Wv, const float* __restrict__ Wg,
    const float* __restrict__ Wo)
{
    if (blockIdx.x < 256) {
        int idx = blockIdx.x * 256 + threadIdx.x;
        int k = idx >> 9;
        int n = idx & 511;
        const float* W = (n < 128) ? Wq : (n < 256) ? Wk : (n < 384) ? Wv : Wg;
        float w = W[k * 128 + (n & 127)];
        __nv_bfloat16 h = bhi(w);
        g_B_hi[idx] = h;
        g_B_lo[idx] = blo(w, h);
    } else {
        int idx = (blockIdx.x - 256) * 256 + threadIdx.x;
        float w = Wo[idx];
        __nv_bfloat16 h = bhi(w);
        g_Wo_hi[idx] = h;
        g_Wo_lo[idx] = blo(w, h);
    }
}

// ============================= proj =============================
// A hi/lo in smem; B staged per 64-col chunk -> occ 2.
// q/k chunks: 2-pass (hh + loA*hiB); v/gate: 3-pass.
#define LDA 136
#define LDB2 72
#define A_HI_OFF 0
#define A_LO_OFF (128 * LDA * 2)
#define B_HI_OFF (2 * 128 * LDA * 2)              // 69632
#define B_LO_OFF (B_HI_OFF + 128 * LDB2 * 2)
#define PROJ_SMEM (B_LO_OFF + 128 * LDB2 * 2)     // 106496
#define STAGE_OFF B_HI_OFF                         // fp32 [128][68]

__global__ void __launch_bounds__(256, 2) proj_wmma_kernel(
    const float* __restrict__ pair,
    const float* __restrict__ gamma, const float* __restrict__ beta,
    const float* __restrict__ Wb, const float* __restrict__ bg)
{
    extern __shared__ char smem[];
    __nv_bfloat16* sAhi = reinterpret_cast<__nv_bfloat16*>(smem + A_HI_OFF);
    __nv_bfloat16* sAlo = reinterpret_cast<__nv_bfloat16*>(smem + A_LO_OFF);
    __nv_bfloat16* sBhi = reinterpret_cast<__nv_bfloat16*>(smem + B_HI_OFF);
    __nv_bfloat16* sBlo = reinterpret_cast<__nv_bfloat16*>(smem + B_LO_OFF);
    float* stage = reinterpret_cast<float*>(smem + STAGE_OFF);

    const int t = threadIdx.x;
    const int wid = t >> 5, lane = t & 31;
    const int row0 = blockIdx.x * 128;

    float4 gv = reinterpret_cast<const float4*>(gamma)[lane];
    float4 bv = reinterpret_cast<const float4*>(beta)[lane];
    float4 wbr[4];
#pragma unroll
    for (int i = 0; i < 4; ++i)
        wbr[i] = *reinterpret_cast<const float4*>(Wb + (lane * 4 + i) * 4);

#pragma unroll 2
    for (int rr = 0; rr < 16; ++rr) {
        int r = wid * 16 + rr;
        float4 x = reinterpret_cast<const float4*>(pair + (size_t)(row0 + r) * D)[lane];
        float s  = x.x + x.y + x.z + x.w;
        float s2 = x.x * x.x + x.y * x.y + x.z * x.z + x.w * x.w;
#pragma unroll
        for (int o = 16; o > 0; o >>= 1) {
            s  += __shfl_xor_sync(0xffffffffu, s,  o);
            s2 += __shfl_xor_sync(0xffffffffu, s2, o);
        }
        float mu  = s * (1.0f / 128.0f);
        float var = s2 * (1.0f / 128.0f) - mu * mu;
        float rs  = rsqrtf(var + 1e-5f);
        float4 xn;
        xn.x = (x.x - mu) * rs * gv.x + bv.x;
        xn.y = (x.y - mu) * rs * gv.y + bv.y;
        xn.z = (x.z - mu) * rs * gv.z + bv.z;
        xn.w = (x.w - mu) * rs * gv.w + bv.w;

        __nv_bfloat16 h0 = bhi(xn.x), h1 = bhi(xn.y), h2 = bhi(xn.z), h3 = bhi(xn.w);
        size_t aoff = (size_t)r * LDA + lane * 4;
        reinterpret_cast<__nv_bfloat162*>(sAhi + aoff)[0] = {h0, h1};
        reinterpret_cast<__nv_bfloat162*>(sAhi + aoff)[1] = {h2, h3};
        reinterpret_cast<__nv_bfloat162*>(sAlo + aoff)[0] = {blo(xn.x, h0), blo(xn.y, h1)};
        reinterpret_cast<__nv_bfloat162*>(sAlo + aoff)[1] = {blo(xn.z, h2), blo(xn.w, h3)};

        float4 bacc;
        bacc.x = xn.x * wbr[0].x + xn.y * wbr[1].x + xn.z * wbr[2].x + xn.w * wbr[3].x;
        bacc.y = xn.x * wbr[0].y + xn.y * wbr[1].y + xn.z * wbr[2].y + xn.w * wbr[3].y;
        bacc.z = xn.x * wbr[0].z + xn.y * wbr[1].z + xn.z * wbr[2].z + xn.w * wbr[3].z;
        bacc.w = xn.x * wbr[0].w + xn.y * wbr[1].w + xn.z * wbr[2].w + xn.w * wbr[3].w;
#pragma unroll
        for (int o = 16; o > 0; o >>= 1) {
            bacc.x += __shfl_xor_sync(0xffffffffu, bacc.x, o);
            bacc.y += __shfl_xor_sync(0xffffffffu, bacc.y, o);
            bacc.z += __shfl_xor_sync(0xffffffffu, bacc.z, o);
            bacc.w += __shfl_xor_sync(0xffffffffu, bacc.w, o);
        }
        if (lane == 0) {
            int p = row0 + r;
            g_biasH[0 * 65536 + p] = bacc.x;
            g_biasH[1 * 65536 + p] = bacc.y;
            g_biasH[2 * 65536 + p] = bacc.z;
            g_biasH[3 * 65536 + p] = bacc.w;
        }
    }

    const int wm = (wid & 3) * 32;
    const int wn = (wid >> 2) * 32;

    for (int c = 0; c < 8; ++c) {
        const bool three = (c >= 4);   // v and gate need the W_lo correction
        __syncthreads();               // prior chunk's B/stage reads done
#pragma unroll
        for (int it = 0; it < 4; ++it) {
            int idx = it * 256 + t;
            int k = idx >> 3, u = idx & 7;
            size_t src = (size_t)k * 512 + c * 64 + u * 8;
            size_t dst = (size_t)k * LDB2 + u * 8;
            *reinterpret_cast<uint4*>(sBhi + dst) = *reinterpret_cast<const uint4*>(g_B_hi + src);
            *reinterpret_cast<uint4*>(sBlo + dst) = *reinterpret_cast<const uint4*>(g_B_lo + src);
        }
        __syncthreads();

        wmma::fragment<wmma::accumulator, 16, 16, 16, float> acc[2][2];
#pragma unroll
        for (int i = 0; i < 2; ++i)
#pragma unroll
            for (int j = 0; j < 2; ++j) wmma::fill_fragment(acc[i][j], 0.0f);

#pragma unroll
        for (int k8 = 0; k8 < 8; ++k8) {
            wmma::fragment<wmma::matrix_a, 16, 16, 16, __nv_bfloat16, wmma::row_major> afh[2], afl[2];
            wmma::load_matrix_sync(afh[0], sAhi + (size_t)(wm +  0) * LDA + k8 * 16, LDA);
            wmma::load_matrix_sync(afh[1], sAhi + (size_t)(wm + 16) * LDA + k8 * 16, LDA);
            wmma::load_matrix_sync(afl[0], sAlo + (size_t)(wm +  0) * LDA + k8 * 16, LDA);
            wmma::load_matrix_sync(afl[1], sAlo + (size_t)(wm + 16) * LDA + k8 * 16, LDA);
#pragma unroll
            for (int j = 0; j < 2; ++j) {
                wmma::fragment<wmma::matrix_b, 16, 16, 16, __nv_bfloat16, wmma::row_major> bfh;
                wmma::load_matrix_sync(bfh, sBhi + (size_t)(k8 * 16) * LDB2 + wn + j * 16, LDB2);
                wmma::mma_sync(acc[0][j], afh[0], bfh, acc[0][j]);
                wmma::mma_sync(acc[1][j], afh[1], bfh, acc[1][j]);
                wmma::mma_sync(acc[0][j], afl[0], bfh, acc[0][j]);
                wmma::mma_sync(acc[1][j], afl[1], bfh, acc[1][j]);
                if (three) {
                    wmma::fragment<wmma::matrix_b, 16, 16, 16, __nv_bfloat16, wmma::row_major> bfl;
                    wmma::load_matrix_sync(bfl, sBlo + (size_t)(k8 * 16) * LDB2 + wn + j * 16, LDB2);
                    wmma::mma_sync(acc[0][j], afh[0], bfl, acc[0][j]);
                    wmma::mma_sync(acc[1][j], afh[1], bfl, acc[1][j]);
                }
            }
        }

        if (c < 6) {
            float* dst = (c < 2) ? g_q : (c < 4) ? g_k : g_v;
            int coloff = (c & 1) * 64;
            if (c < 2) {
#pragma unroll
                for (int i = 0; i < 2; ++i)
#pragma unroll
                    for (int j = 0; j < 2; ++j)
#pragma unroll
                        for (int e = 0; e < acc[i][j].num_elements; ++e)
                            acc[i][j].x[e] *= SCALING;
            }
#pragma unroll
            for (int i = 0; i < 2; ++i)
#pragma unroll
                for (int j = 0; j < 2; ++j)
                    wmma::store_matrix_sync(
                        dst + (size_t)(row0 + wm + i * 16) * D + coloff + wn + j * 16,
                        acc[i][j], D, wmma::mem_row_major);
        } else {
            int coloff = (c - 6) * 64;
            __syncthreads();
#pragma unroll
            for (int i = 0; i < 2; ++i)
#pragma unroll
                for (int j = 0; j < 2; ++j)
                    wmma::store_matrix_sync(
                        stage + (size_t)(wm + i * 16) * 68 + wn + j * 16,
                        acc[i][j], 68, wmma::mem_row_major);
            __syncthreads();
#pragma unroll
            for (int it = 0; it < 8; ++it) {
                int idx = it * 256 + t;
                int r = idx >> 4, q = idx & 15;
                float4 v = *reinterpret_cast<const float4*>(stage + (size_t)r * 68 + q * 4);
                float4 bgv = *reinterpret_cast<const float4*>(bg + coloff + q * 4);
                float4 o;
                o.x = 1.0f / (1.0f + __expf(-(v.x + bgv.x)));
                o.y = 1.0f / (1.0f + __expf(-(v.y + bgv.y)));
                o.z = 1.0f / (1.0f + __expf(-(v.z + bgv.z)));
                o.w = 1.0f / (1.0f + __expf(-(v.w + bgv.w)));
                *reinterpret_cast<float4*>(g_gate + (size_t)(row0 + r) * D + coloff + q * 4) = o;
            }
        }
    }
}

// ============================= attn =============================
// Per-chunk St/Pt producer-consumer pairs are warp-private -> __syncwarp
// replaces all per-chunk block barriers; warps free-run over 16 chunks.
#define LDQ 40
#define LDSS 260
#define LDP2 264
#define LDO 36
#define AQH 0
#define AKB 20480
#define AVH 40960
#define AVL 61440
#define AST 81920
#define APH 98560
#define APL 107008
#define ATTN_SMEM 115456

__global__ void __launch_bounds__(256, 2) attn_wmma_kernel()
{
    extern __shared__ char smem[];
    __nv_bfloat16* Qh  = reinterpret_cast<__nv_bfloat16*>(smem + AQH);
    __nv_bfloat16* Kb  = reinterpret_cast<__nv_bfloat16*>(smem + AKB);
    __nv_bfloat16* Vh  = reinterpret_cast<__nv_bfloat16*>(smem + AVH);
    __nv_bfloat16* Vl  = reinterpret_cast<__nv_bfloat16*>(smem + AVL);
    float*         St  = reinterpret_cast<float*>(smem + AST);
    __nv_bfloat16* Pth = reinterpret_cast<__nv_bfloat16*>(smem + APH);
    __nv_bfloat16* Ptl = reinterpret_cast<__nv_bfloat16*>(smem + APL);
    float*       Sout  = reinterpret_cast<float*>(smem + 0);

    const int i = blockIdx.x;
    const int h = blockIdx.y;
    const int t = threadIdx.x;
    const int w = t >> 5;
    const size_t gbase = (size_t)i * 256 * 128 + h * 32;

#pragma unroll
    for (int u = 0; u < 8; ++u) {
        int idx = u * 256 + t;
        int row = idx >> 3, c4 = idx & 7;
        size_t goff = gbase + (size_t)row * 128 + c4 * 4;
        size_t soff = (size_t)row * LDQ + c4 * 4;
        float4 q4 = *reinterpret_cast<const float4*>(g_q + goff);
        float4 k4 = *reinterpret_cast<const float4*>(g_k + goff);
        float4 v4 = *reinterpret_cast<const float4*>(g_v + goff);
        reinterpret_cast<__nv_bfloat162*>(Qh + soff)[0] = {bhi(q4.x), bhi(q4.y)};
        reinterpret_cast<__nv_bfloat162*>(Qh + soff)[1] = {bhi(q4.z), bhi(q4.w)};
        reinterpret_cast<__nv_bfloat162*>(Kb + soff)[0] = {bhi(k4.x), bhi(k4.y)};
        reinterpret_cast<__nv_bfloat162*>(Kb + soff)[1] = {bhi(k4.z), bhi(k4.w)};
        __nv_bfloat16 vh0 = bhi(v4.x), vh1 = bhi(v4.y), vh2 = bhi(v4.z), vh3 = bhi(v4.w);
        reinterpret_cast<__nv_bfloat162*>(Vh + soff)[0] = {vh0, vh1};
        reinterpret_cast<__nv_bfloat162*>(Vh + soff)[1] = {vh2, vh3};
        reinterpret_cast<__nv_bfloat162*>(Vl + soff)[0] = {blo(v4.x, vh0), blo(v4.y, vh1)};
        reinterpret_cast<__nv_bfloat162*>(Vl + soff)[1] = {blo(v4.z, vh2), blo(v4.w, vh3)};
    }
    __syncthreads();

    const float* biasp = g_biasH + (size_t)h * 65536;
    const int j0w = w * 32;

    wmma::fragment<wmma::accumulator, 16, 16, 16, float> acc_o[2][2];
#pragma unroll
    for (int a = 0; a < 2; ++a)
#pragma unroll
        for (int b = 0; b < 2; ++b) wmma::fill_fragment(acc_o[a][b], 0.0f);
    float ssum = 0.0f;

    for (int c = 0; c < 16; ++c) {
        const int k0c = c * 16;

        // ---- S = bias + Qh K^T (warp-private St columns) ----
        wmma::fragment<wmma::accumulator, 16, 16, 16, float> accs[2];
#pragma unroll
        for (int a = 0; a < 2; ++a)
            wmma::load_matrix_sync(accs[a],
                biasp + (size_t)(j0w + a * 16) * 256 + k0c, 256, wmma::mem_row_major);
#pragma unroll
        for (int s = 0; s < 2; ++s) {
            wmma::fragment<wmma::matrix_b, 16, 16, 16, __nv_bfloat16, wmma::col_major> kf;
            wmma::load_matrix_sync(kf, Kb + (size_t)k0c * LDQ + s * 16, LDQ);
            wmma::fragment<wmma::matrix_a, 16, 16, 16, __nv_bfloat16, wmma::row_major> af[2];
            wmma::load_matrix_sync(af[0], Qh + (size_t)(j0w +  0) * LDQ + s * 16, LDQ);
            wmma::load_matrix_sync(af[1], Qh + (size_t)(j0w + 16) * LDQ + s * 16, LDQ);
            wmma::mma_sync(accs[0], af[0], kf, accs[0]);
            wmma::mma_sync(accs[1], af[1], kf, accs[1]);
        }
#pragma unroll
        for (int a = 0; a < 2; ++a)
            wmma::store_matrix_sync(St + j0w + a * 16, accs[a], LDSS, wmma::mem_col_major);
        __syncwarp();

        // ---- exp: thread t owns column t (within this warp's range) ----
        {
            float acc = 0.0f;
#pragma unroll 4
            for (int kk = 0; kk < 16; ++kk) {
                float p = __expf(St[(size_t)kk * LDSS + t]);
                acc += p;
                __nv_bfloat16 ph = bhi(p);
                Pth[(size_t)kk * LDP2 + t] = ph;
                Ptl[(size_t)kk * LDP2 + t] = blo(p, ph);
            }
            ssum += acc;
        }
        __syncwarp();

        // ---- out += Ph Vh + Pl Vh + Ph Vl (warp-private Pt columns) ----
        wmma::fragment<wmma::matrix_a, 16, 16, 16, __nv_bfloat16, wmma::col_major> aph[2], apl[2];
#pragma unroll
        for (int a = 0; a < 2; ++a) {
            wmma::load_matrix_sync(aph[a], Pth + j0w + a * 16, LDP2);
            wmma::load_matrix_sync(apl[a], Ptl + j0w + a * 16, LDP2);
        }
#pragma unroll
        for (int b = 0; b < 2; ++b) {
            wmma::fragment<wmma::matrix_b, 16, 16, 16, __nv_bfloat16, wmma::row_major> vfh, vfl;
            wmma::load_matrix_sync(vfh, Vh + (size_t)k0c * LDQ + b * 16, LDQ);
            wmma::load_matrix_sync(vfl, Vl + (size_t)k0c * LDQ + b * 16, LDQ);
#pragma unroll
            for (int a = 0; a < 2; ++a) {
                wmma::mma_sync(acc_o[a][b], aph[a], vfh, acc_o[a][b]);
                wmma::mma_sync(acc_o[a][b], apl[a], vfh, acc_o[a][b]);
                wmma::mma_sync(acc_o[a][b], aph[a], vfl, acc_o[a][b]);
            }
        }
    }

    __syncthreads();   // all warps done reading Qh/Kb before Sout overwrites region 0
#pragma unroll
    for (int a = 0; a < 2; ++a)
#pragma unroll
        for (int b = 0; b < 2; ++b)
            wmma::store_matrix_sync(Sout + (size_t)(j0w + a * 16) * LDO + b * 16,
                                    acc_o[a][b], LDO, wmma::mem_row_major);
    __syncwarp();      // Sout rows j0w..j0w+31 read back by this warp only

    {
        float inv = 1.0f / ssum;
        const float* gp = g_gate + gbase + (size_t)t * 128;
        __nv_bfloat16* yh = g_y_hi + gbase + (size_t)t * 128;
        __nv_bfloat16* yl = g_y_lo + gbase + (size_t)t * 128;
#pragma unroll
        for (int d4 = 0; d4 < 8; ++d4) {
            float4 v = *reinterpret_cast<const float4*>(Sout + (size_t)t * LDO + d4 * 4);
            float4 g = *reinterpret_cast<const float4*>(gp + d4 * 4);
            float4 y = {v.x * inv * g.x, v.y * inv * g.y, v.z * inv * g.z, v.w * inv * g.w};
            __nv_bfloat16 h0 = bhi(y.x), h1 = bhi(y.y), h2 = bhi(y.z), h3 = bhi(y.w);
            reinterpret_cast<__nv_bfloat162*>(yh + d4 * 4)[0] = {h0, h1};
            reinterpret_cast<__nv_bfloat162*>(yh + d4 * 4)[1] = {h2, h3};
            reinterpret_cast<__nv_bfloat162*>(yl + d4 * 4)[0] = {blo(y.x, h0), blo(y.y, h1)};
            reinterpret_cast<__nv_bfloat162*>(yl + d4 * 4)[1] = {blo(y.z, h2), blo(y.w, h3)};
        }
    }
}

// ============================= epi =============================
#define E_LDB 72
#define E_AHI 0
#define E_ALO (128 * 136 * 2)
#define E_BHI (2 * 128 * 136 * 2)                 // 69632
#define E_BLO (E_BHI + 128 * E_LDB * 2)
#define EPI_SMEM (E_BLO + 128 * E_LDB * 2)        // 106496
#define E_STAGE E_BHI

__global__ void __launch_bounds__(256, 2) epi_wmma_kernel(
    const float* __restrict__ bo, float* __restrict__ out)
{
    extern __shared__ char smem[];
    __nv_bfloat16* sAhi = reinterpret_cast<__nv_bfloat16*>(smem + E_AHI);
    __nv_bfloat16* sAlo = reinterpret_cast<__nv_bfloat16*>(smem + E_ALO);
    __nv_bfloat16* sBhi = reinterpret_cast<__nv_bfloat16*>(smem + E_BHI);
    __nv_bfloat16* sBlo = reinterpret_cast<__nv_bfloat16*>(smem + E_BLO);
    float* stage = reinterpret_cast<float*>(smem + E_STAGE);

    const int t = threadIdx.x;
    const int wid = t >> 5;
    const int row0 = blockIdx.x * 128;

#pragma unroll
    for (int it = 0; it < 8; ++it) {
        int idx = it * 256 + t;
        int r = idx >> 4, u = idx & 15;
        size_t src = (size_t)(row0 + r) * D + u * 8;
        size_t dst = (size_t)r * 136 + u * 8;
        *reinterpret_cast<uint4*>(sAhi + dst) = *reinterpret_cast<const uint4*>(g_y_hi + src);
        *reinterpret_cast<uint4*>(sAlo + dst) = *reinterpret_cast<const uint4*>(g_y_lo + src);
    }

    const int wm = (wid & 3) * 32;
    const int wn = (wid >> 2) * 32;

    for (int c = 0; c < 2; ++c) {
        __syncthreads();
#pragma unroll
        for (int it = 0; it < 4; ++it) {
            int idx = it * 256 + t;
            int k = idx >> 3, u = idx & 7;
            size_t src = (size_t)k * 128 + c * 64 + u * 8;
            size_t dst = (size_t)k * E_LDB + u * 8;
            *reinterpret_cast<uint4*>(sBhi + dst) = *reinterpret_cast<const uint4*>(g_Wo_hi + src);
            *reinterpret_cast<uint4*>(sBlo + dst) = *reinterpret_cast<const uint4*>(g_Wo_lo + src);
        }
        __syncthreads();

        wmma::fragment<wmma::accumulator, 16, 16, 16, float> acc[2][2];
#pragma unroll
        for (int i = 0; i < 2; ++i)
#pragma unroll
            for (int j = 0; j < 2; ++j) wmma::fill_fragment(acc[i][j], 0.0f);

#pragma unroll
        for (int k8 = 0; k8 < 8; ++k8) {
            wmma::fragment<wmma::matrix_a, 16, 16, 16, __nv_bfloat16, wmma::row_major> afh[2], afl[2];
            wmma::load_matrix_sync(afh[0], sAhi + (size_t)(wm +  0) * 136 + k8 * 16, 136);
            wmma::load_matrix_sync(afh[1], sAhi + (size_t)(wm + 16) * 136 + k8 * 16, 136);
            wmma::load_matrix_sync(afl[0], sAlo + (size_t)(wm +  0) * 136 + k8 * 16, 136);
            wmma::load_matrix_sync(afl[1], sAlo + (size_t)(wm + 16) * 136 + k8 * 16, 136);
#pragma unroll
            for (int j = 0; j < 2; ++j) {
                wmma::fragment<wmma::matrix_b, 16, 16, 16, __nv_bfloat16, wmma::row_major> bfh, bfl;
                wmma::load_matrix_sync(bfh, sBhi + (size_t)(k8 * 16) * E_LDB + wn + j * 16, E_LDB);
                wmma::load_matrix_sync(bfl, sBlo + (size_t)(k8 * 16) * E_LDB + wn + j * 16, E_LDB);
                wmma::mma_sync(acc[0][j], afh[0], bfh, acc[0][j]);
                wmma::mma_sync(acc[1][j], afh[1], bfh, acc[1][j]);
                wmma::mma_sync(acc[0][j], afl[0], bfh, acc[0][j]);
                wmma::mma_sync(acc[1][j], afl[1], bfh, acc[1][j]);
                wmma::mma_sync(acc[0][j], afh[0], bfl, acc[0][j]);
                wmma::mma_sync(acc[1][j], afh[1], bfl, acc[1][j]);
            }
        }

        __syncthreads();
#pragma unroll
        for (int i = 0; i < 2; ++i)
#pragma unroll
            for (int j = 0; j < 2; ++j)
                wmma::store_matrix_sync(stage + (size_t)(wm + i * 16) * 68 + wn + j * 16,
                                        acc[i][j], 68, wmma::mem_row_major);
        __syncthreads();

#pragma unroll
        for (int it = 0; it < 8; ++it) {
            int idx = it * 256 + t;
            int r = idx >> 4, q = idx & 15;
            float4 v = *reinterpret_cast<const float4*>(stage + (size_t)r * 68 + q * 4);
            float4 b = *reinterpret_cast<const float4*>(bo + c * 64 + q * 4);
            v.x += b.x; v.y += b.y; v.z += b.z; v.w += b.w;
            *reinterpret_cast<float4*>(out + (size_t)(row0 + r) * D + c * 64 + q * 4) = v;
        }
    }
}

extern "C" void kernel_launch(void* const* d_in, const int* in_sizes, int n_in,
                              void* d_out, int out_size)
{
    const float* pair  = (const float*)d_in[0];
    const float* gamma = (const float*)d_in[1];
    const float* beta  = (const float*)d_in[2];
    const float* Wq    = (const float*)d_in[3];
    const float* Wk    = (const float*)d_in[4];
    const float* Wv    = (const float*)d_in[5];
    const float* Wb    = (const float*)d_in[6];
    const float* Wg    = (const float*)d_in[7];
    const float* bg    = (const float*)d_in[8];
    const float* Wo    = (const float*)d_in[9];
    const float* bo    = (const float*)d_in[10];
    float* out = (float*)d_out;

    cudaFuncSetAttribute(proj_wmma_kernel, cudaFuncAttributeMaxDynamicSharedMemorySize, PROJ_SMEM);
    cudaFuncSetAttribute(attn_wmma_kernel, cudaFuncAttributeMaxDynamicSharedMemorySize, ATTN_SMEM);
    cudaFuncSetAttribute(epi_wmma_kernel,  cudaFuncAttributeMaxDynamicSharedMemorySize, EPI_SMEM);

    prep_kernel<<<320, 256>>>(Wq, Wk, Wv, Wg, Wo);
    proj_wmma_kernel<<<(L * L) / 128, 256, PROJ_SMEM>>>(pair, gamma, beta, Wb, bg);
    attn_wmma_kernel<<<dim3(L, H), 256, ATTN_SMEM>>>();
    epi_wmma_kernel<<<(L * L) / 128, 256, EPI_SMEM>>>(bo, out);
}

// round 16
// speedup vs baseline: 1.5313x; 1.0735x over previous
#include <cuda_runtime.h>
#include <cuda_bf16.h>
#include <mma.h>
#include <cstdint>

using namespace nvcuda;

#define L 256
#define D 128
#define H 4
#define SCALING 0.17677669529663687f

// ---- scratch ----
__device__ __align__(16) float g_q[L * L * D];
__device__ __align__(16) float g_k[L * L * D];
__device__ __align__(16) float g_v[L * L * D];
__device__ __align__(16) float g_gate[L * L * D];
__device__ __align__(16) float g_biasH[H * L * L];            // [h][j][k]
__device__ __align__(16) __nv_bfloat16 g_y_hi[L * L * D];     // gate*att, bf16 hi
__device__ __align__(16) __nv_bfloat16 g_y_lo[L * L * D];     // bf16 lo
__device__ __align__(16) __nv_bfloat16 g_B_hi[128 * 512];     // [k][n] (Wq|Wk|Wv|Wg)
__device__ __align__(16) __nv_bfloat16 g_B_lo[128 * 512];
__device__ __align__(16) __nv_bfloat16 g_Wo_hi[128 * 128];    // [k][n]
__device__ __align__(16) __nv_bfloat16 g_Wo_lo[128 * 128];

__device__ __forceinline__ __nv_bfloat16 bhi(float x) { return __float2bfloat16_rn(x); }
__device__ __forceinline__ __nv_bfloat16 blo(float x, __nv_bfloat16 h) {
    return __float2bfloat16_rn(x - __bfloat162float(h));
}

// ---- prep ----
__global__ void __launch_bounds__(256) prep_kernel(
    const float* __restrict__ Wq, const float* __restrict__ Wk,
    const float* __restrict__ Wv, const float* __restrict__ Wg,
    const float* __restrict__ Wo)
{
    if (blockIdx.x < 256) {
        int idx = blockIdx.x * 256 + threadIdx.x;
        int k = idx >> 9;
        int n = idx & 511;
        const float* W = (n < 128) ? Wq : (n < 256) ? Wk : (n < 384) ? Wv : Wg;
        float w = W[k * 128 + (n & 127)];
        __nv_bfloat16 h = bhi(w);
        g_B_hi[idx] = h;
        g_B_lo[idx] = blo(w, h);
    } else {
        int idx = (blockIdx.x - 256) * 256 + threadIdx.x;
        float w = Wo[idx];
        __nv_bfloat16 h = bhi(w);
        g_Wo_hi[idx] = h;
        g_Wo_lo[idx] = blo(w, h);
    }
}

// ============================= proj =============================
// r10 + gate chunks (c=6,7) reduced to 2-pass; v (c=4,5) keeps 3-pass.
#define LDA 136
#define LDB2 72
#define A_HI_OFF 0
#define A_LO_OFF (128 * LDA * 2)
#define B_HI_OFF (2 * 128 * LDA * 2)              // 69632
#define B_LO_OFF (B_HI_OFF + 128 * LDB2 * 2)
#define PROJ_SMEM (B_LO_OFF + 128 * LDB2 * 2)     // 106496
#define STAGE_OFF B_HI_OFF                         // fp32 [128][68]

__global__ void __launch_bounds__(256, 2) proj_wmma_kernel(
    const float* __restrict__ pair,
    const float* __restrict__ gamma, const float* __restrict__ beta,
    const float* __restrict__ Wb, const float* __restrict__ bg)
{
    extern __shared__ char smem[];
    __nv_bfloat16* sAhi = reinterpret_cast<__nv_bfloat16*>(smem + A_HI_OFF);
    __nv_bfloat16* sAlo = reinterpret_cast<__nv_bfloat16*>(smem + A_LO_OFF);
    __nv_bfloat16* sBhi = reinterpret_cast<__nv_bfloat16*>(smem + B_HI_OFF);
    __nv_bfloat16* sBlo = reinterpret_cast<__nv_bfloat16*>(smem + B_LO_OFF);
    float* stage = reinterpret_cast<float*>(smem + STAGE_OFF);

    const int t = threadIdx.x;
    const int wid = t >> 5, lane = t & 31;
    const int row0 = blockIdx.x * 128;

    float4 gv = reinterpret_cast<const float4*>(gamma)[lane];
    float4 bv = reinterpret_cast<const float4*>(beta)[lane];
    float4 wbr[4];
#pragma unroll
    for (int i = 0; i < 4; ++i)
        wbr[i] = *reinterpret_cast<const float4*>(Wb + (lane * 4 + i) * 4);

#pragma unroll 2
    for (int rr = 0; rr < 16; ++rr) {
        int r = wid * 16 + rr;
        float4 x = reinterpret_cast<const float4*>(pair + (size_t)(row0 + r) * D)[lane];
        float s  = x.x + x.y + x.z + x.w;
        float s2 = x.x * x.x + x.y * x.y + x.z * x.z + x.w * x.w;
#pragma unroll
        for (int o = 16; o > 0; o >>= 1) {
            s  += __shfl_xor_sync(0xffffffffu, s,  o);
            s2 += __shfl_xor_sync(0xffffffffu, s2, o);
        }
        float mu  = s * (1.0f / 128.0f);
        float var = s2 * (1.0f / 128.0f) - mu * mu;
        float rs  = rsqrtf(var + 1e-5f);
        float4 xn;
        xn.x = (x.x - mu) * rs * gv.x + bv.x;
        xn.y = (x.y - mu) * rs * gv.y + bv.y;
        xn.z = (x.z - mu) * rs * gv.z + bv.z;
        xn.w = (x.w - mu) * rs * gv.w + bv.w;

        __nv_bfloat16 h0 = bhi(xn.x), h1 = bhi(xn.y), h2 = bhi(xn.z), h3 = bhi(xn.w);
        size_t aoff = (size_t)r * LDA + lane * 4;
        reinterpret_cast<__nv_bfloat162*>(sAhi + aoff)[0] = {h0, h1};
        reinterpret_cast<__nv_bfloat162*>(sAhi + aoff)[1] = {h2, h3};
        reinterpret_cast<__nv_bfloat162*>(sAlo + aoff)[0] = {blo(xn.x, h0), blo(xn.y, h1)};
        reinterpret_cast<__nv_bfloat162*>(sAlo + aoff)[1] = {blo(xn.z, h2), blo(xn.w, h3)};

        float4 bacc;
        bacc.x = xn.x * wbr[0].x + xn.y * wbr[1].x + xn.z * wbr[2].x + xn.w * wbr[3].x;
        bacc.y = xn.x * wbr[0].y + xn.y * wbr[1].y + xn.z * wbr[2].y + xn.w * wbr[3].y;
        bacc.z = xn.x * wbr[0].z + xn.y * wbr[1].z + xn.z * wbr[2].z + xn.w * wbr[3].z;
        bacc.w = xn.x * wbr[0].w + xn.y * wbr[1].w + xn.z * wbr[2].w + xn.w * wbr[3].w;
#pragma unroll
        for (int o = 16; o > 0; o >>= 1) {
            bacc.x += __shfl_xor_sync(0xffffffffu, bacc.x, o);
            bacc.y += __shfl_xor_sync(0xffffffffu, bacc.y, o);
            bacc.z += __shfl_xor_sync(0xffffffffu, bacc.z, o);
            bacc.w += __shfl_xor_sync(0xffffffffu, bacc.w, o);
        }
        if (lane == 0) {
            int p = row0 + r;
            g_biasH[0 * 65536 + p] = bacc.x;
            g_biasH[1 * 65536 + p] = bacc.y;
            g_biasH[2 * 65536 + p] = bacc.z;
            g_biasH[3 * 65536 + p] = bacc.w;
        }
    }

    const int wm = (wid & 3) * 32;
    const int wn = (wid >> 2) * 32;

    for (int c = 0; c < 8; ++c) {
        const bool three = (c == 4 || c == 5);   // only v needs the W_lo correction
        __syncthreads();               // prior chunk's B/stage reads done
#pragma unroll
        for (int it = 0; it < 4; ++it) {
            int idx = it * 256 + t;
            int k = idx >> 3, u = idx & 7;
            size_t src = (size_t)k * 512 + c * 64 + u * 8;
            size_t dst = (size_t)k * LDB2 + u * 8;
            *reinterpret_cast<uint4*>(sBhi + dst) = *reinterpret_cast<const uint4*>(g_B_hi + src);
            *reinterpret_cast<uint4*>(sBlo + dst) = *reinterpret_cast<const uint4*>(g_B_lo + src);
        }
        __syncthreads();

        wmma::fragment<wmma::accumulator, 16, 16, 16, float> acc[2][2];
#pragma unroll
        for (int i = 0; i < 2; ++i)
#pragma unroll
            for (int j = 0; j < 2; ++j) wmma::fill_fragment(acc[i][j], 0.0f);

#pragma unroll
        for (int k8 = 0; k8 < 8; ++k8) {
            wmma::fragment<wmma::matrix_a, 16, 16, 16, __nv_bfloat16, wmma::row_major> afh[2], afl[2];
            wmma::load_matrix_sync(afh[0], sAhi + (size_t)(wm +  0) * LDA + k8 * 16, LDA);
            wmma::load_matrix_sync(afh[1], sAhi + (size_t)(wm + 16) * LDA + k8 * 16, LDA);
            wmma::load_matrix_sync(afl[0], sAlo + (size_t)(wm +  0) * LDA + k8 * 16, LDA);
            wmma::load_matrix_sync(afl[1], sAlo + (size_t)(wm + 16) * LDA + k8 * 16, LDA);
#pragma unroll
            for (int j = 0; j < 2; ++j) {
                wmma::fragment<wmma::matrix_b, 16, 16, 16, __nv_bfloat16, wmma::row_major> bfh;
                wmma::load_matrix_sync(bfh, sBhi + (size_t)(k8 * 16) * LDB2 + wn + j * 16, LDB2);
                wmma::mma_sync(acc[0][j], afh[0], bfh, acc[0][j]);
                wmma::mma_sync(acc[1][j], afh[1], bfh, acc[1][j]);
                wmma::mma_sync(acc[0][j], afl[0], bfh, acc[0][j]);
                wmma::mma_sync(acc[1][j], afl[1], bfh, acc[1][j]);
                if (three) {
                    wmma::fragment<wmma::matrix_b, 16, 16, 16, __nv_bfloat16, wmma::row_major> bfl;
                    wmma::load_matrix_sync(bfl, sBlo + (size_t)(k8 * 16) * LDB2 + wn + j * 16, LDB2);
                    wmma::mma_sync(acc[0][j], afh[0], bfl, acc[0][j]);
                    wmma::mma_sync(acc[1][j], afh[1], bfl, acc[1][j]);
                }
            }
        }

        if (c < 6) {
            float* dst = (c < 2) ? g_q : (c < 4) ? g_k : g_v;
            int coloff = (c & 1) * 64;
            if (c < 2) {
#pragma unroll
                for (int i = 0; i < 2; ++i)
#pragma unroll
                    for (int j = 0; j < 2; ++j)
#pragma unroll
                        for (int e = 0; e < acc[i][j].num_elements; ++e)
                            acc[i][j].x[e] *= SCALING;
            }
#pragma unroll
            for (int i = 0; i < 2; ++i)
#pragma unroll
                for (int j = 0; j < 2; ++j)
                    wmma::store_matrix_sync(
                        dst + (size_t)(row0 + wm + i * 16) * D + coloff + wn + j * 16,
                        acc[i][j], D, wmma::mem_row_major);
        } else {
            int coloff = (c - 6) * 64;
            __syncthreads();
#pragma unroll
            for (int i = 0; i < 2; ++i)
#pragma unroll
                for (int j = 0; j < 2; ++j)
                    wmma::store_matrix_sync(
                        stage + (size_t)(wm + i * 16) * 68 + wn + j * 16,
                        acc[i][j], 68, wmma::mem_row_major);
            __syncthreads();
#pragma unroll
            for (int it = 0; it < 8; ++it) {
                int idx = it * 256 + t;
                int r = idx >> 4, q = idx & 15;
                float4 v = *reinterpret_cast<const float4*>(stage + (size_t)r * 68 + q * 4);
                float4 bgv = *reinterpret_cast<const float4*>(bg + coloff + q * 4);
                float4 o;
                o.x = 1.0f / (1.0f + __expf(-(v.x + bgv.x)));
                o.y = 1.0f / (1.0f + __expf(-(v.y + bgv.y)));
                o.z = 1.0f / (1.0f + __expf(-(v.z + bgv.z)));
                o.w = 1.0f / (1.0f + __expf(-(v.w + bgv.w)));
                *reinterpret_cast<float4*>(g_gate + (size_t)(row0 + r) * D + coloff + q * 4) = o;
            }
        }
    }
}

// ============================= attn =============================
// Centered-P: out = sumV + P' V (P' = exp(s)-1, single bf16).
// PV passes 3 -> 2; Ptl buffer eliminated. Warp-private chunk sync.
#define LDQ 40
#define LDSS 260
#define LDP2 264
#define LDO 36
#define AQH 0
#define AKB 20480
#define AVH 40960
#define AVL 61440
#define AST 81920
#define APH 98560
#define APV 107008                 // partials [8][32] f32 + sumV [32] f32
#define ATTN_SMEM 108288

__global__ void __launch_bounds__(256, 2) attn_wmma_kernel()
{
    extern __shared__ char smem[];
    __nv_bfloat16* Qh  = reinterpret_cast<__nv_bfloat16*>(smem + AQH);
    __nv_bfloat16* Kb  = reinterpret_cast<__nv_bfloat16*>(smem + AKB);
    __nv_bfloat16* Vh  = reinterpret_cast<__nv_bfloat16*>(smem + AVH);
    __nv_bfloat16* Vl  = reinterpret_cast<__nv_bfloat16*>(smem + AVL);
    float*         St  = reinterpret_cast<float*>(smem + AST);
    __nv_bfloat16* Pth = reinterpret_cast<__nv_bfloat16*>(smem + APH);
    float*     partial = reinterpret_cast<float*>(smem + APV);          // [8][32]
    float*        sumV = reinterpret_cast<float*>(smem + APV + 1024);   // [32]
    float*       Sout  = reinterpret_cast<float*>(smem + 0);

    const int i = blockIdx.x;
    const int h = blockIdx.y;
    const int t = threadIdx.x;
    const int w = t >> 5;
    const size_t gbase = (size_t)i * 256 * 128 + h * 32;

#pragma unroll
    for (int u = 0; u < 8; ++u) {
        int idx = u * 256 + t;
        int row = idx >> 3, c4 = idx & 7;
        size_t goff = gbase + (size_t)row * 128 + c4 * 4;
        size_t soff = (size_t)row * LDQ + c4 * 4;
        float4 q4 = *reinterpret_cast<const float4*>(g_q + goff);
        float4 k4 = *reinterpret_cast<const float4*>(g_k + goff);
        float4 v4 = *reinterpret_cast<const float4*>(g_v + goff);
        reinterpret_cast<__nv_bfloat162*>(Qh + soff)[0] = {bhi(q4.x), bhi(q4.y)};
        reinterpret_cast<__nv_bfloat162*>(Qh + soff)[1] = {bhi(q4.z), bhi(q4.w)};
        reinterpret_cast<__nv_bfloat162*>(Kb + soff)[0] = {bhi(k4.x), bhi(k4.y)};
        reinterpret_cast<__nv_bfloat162*>(Kb + soff)[1] = {bhi(k4.z), bhi(k4.w)};
        __nv_bfloat16 vh0 = bhi(v4.x), vh1 = bhi(v4.y), vh2 = bhi(v4.z), vh3 = bhi(v4.w);
        reinterpret_cast<__nv_bfloat162*>(Vh + soff)[0] = {vh0, vh1};
        reinterpret_cast<__nv_bfloat162*>(Vh + soff)[1] = {vh2, vh3};
        reinterpret_cast<__nv_bfloat162*>(Vl + soff)[0] = {blo(v4.x, vh0), blo(v4.y, vh1)};
        reinterpret_cast<__nv_bfloat162*>(Vl + soff)[1] = {blo(v4.z, vh2), blo(v4.w, vh3)};
    }

    // sumV partials: warp w sums k-rows [w*32, w*32+32) of column (lane)
    {
        int lane = t & 31;
        float acc = 0.0f;
        const float* vp = g_v + gbase + (size_t)(w * 32) * 128 + lane;
#pragma unroll 8
        for (int kk = 0; kk < 32; ++kk) acc += vp[(size_t)kk * 128];
        partial[w * 32 + lane] = acc;
    }
    __syncthreads();
    if (t < 32) {
        float s = 0.0f;
#pragma unroll
        for (int w2 = 0; w2 < 8; ++w2) s += partial[w2 * 32 + t];
        sumV[t] = s;
    }
    __syncthreads();

    const float* biasp = g_biasH + (size_t)h * 65536;
    const int j0w = w * 32;

    wmma::fragment<wmma::accumulator, 16, 16, 16, float> acc_o[2][2];
#pragma unroll
    for (int a = 0; a < 2; ++a)
#pragma unroll
        for (int b = 0; b < 2; ++b) wmma::fill_fragment(acc_o[a][b], 0.0f);
    float ssum = 0.0f;

    for (int c = 0; c < 16; ++c) {
        const int k0c = c * 16;

        // ---- S = bias + Qh K^T (warp-private St columns) ----
        wmma::fragment<wmma::accumulator, 16, 16, 16, float> accs[2];
#pragma unroll
        for (int a = 0; a < 2; ++a)
            wmma::load_matrix_sync(accs[a],
                biasp + (size_t)(j0w + a * 16) * 256 + k0c, 256, wmma::mem_row_major);
#pragma unroll
        for (int s = 0; s < 2; ++s) {
            wmma::fragment<wmma::matrix_b, 16, 16, 16, __nv_bfloat16, wmma::col_major> kf;
            wmma::load_matrix_sync(kf, Kb + (size_t)k0c * LDQ + s * 16, LDQ);
            wmma::fragment<wmma::matrix_a, 16, 16, 16, __nv_bfloat16, wmma::row_major> af[2];
            wmma::load_matrix_sync(af[0], Qh + (size_t)(j0w +  0) * LDQ + s * 16, LDQ);
            wmma::load_matrix_sync(af[1], Qh + (size_t)(j0w + 16) * LDQ + s * 16, LDQ);
            wmma::mma_sync(accs[0], af[0], kf, accs[0]);
            wmma::mma_sync(accs[1], af[1], kf, accs[1]);
        }
#pragma unroll
        for (int a = 0; a < 2; ++a)
            wmma::store_matrix_sync(St + j0w + a * 16, accs[a], LDSS, wmma::mem_col_major);
        __syncwarp();

        // ---- exp: thread t owns column j = t; store P' = p - 1 (bf16) ----
        {
            float acc = 0.0f;
#pragma unroll 4
            for (int kk = 0; kk < 16; ++kk) {
                float p = __expf(St[(size_t)kk * LDSS + t]);
                acc += p;
                Pth[(size_t)kk * LDP2 + t] = bhi(p - 1.0f);
            }
            ssum += acc;
        }
        __syncwarp();

        // ---- out += P' Vh + P' Vl ----
        wmma::fragment<wmma::matrix_a, 16, 16, 16, __nv_bfloat16, wmma::col_major> aph[2];
#pragma unroll
        for (int a = 0; a < 2; ++a)
            wmma::load_matrix_sync(aph[a], Pth + j0w + a * 16, LDP2);
#pragma unroll
        for (int b = 0; b < 2; ++b) {
            wmma::fragment<wmma::matrix_b, 16, 16, 16, __nv_bfloat16, wmma::row_major> vfh, vfl;
            wmma::load_matrix_sync(vfh, Vh + (size_t)k0c * LDQ + b * 16, LDQ);
            wmma::load_matrix_sync(vfl, Vl + (size_t)k0c * LDQ + b * 16, LDQ);
#pragma unroll
            for (int a = 0; a < 2; ++a) {
                wmma::mma_sync(acc_o[a][b], aph[a], vfh, acc_o[a][b]);
                wmma::mma_sync(acc_o[a][b], aph[a], vfl, acc_o[a][b]);
            }
        }
    }

    __syncthreads();   // all warps done reading Qh/Kb before Sout overwrites region 0
#pragma unroll
    for (int a = 0; a < 2; ++a)
#pragma unroll
        for (int b = 0; b < 2; ++b)
            wmma::store_matrix_sync(Sout + (size_t)(j0w + a * 16) * LDO + b * 16,
                                    acc_o[a][b], LDO, wmma::mem_row_major);
    __syncwarp();

    {
        float inv = 1.0f / ssum;
        const float* gp = g_gate + gbase + (size_t)t * 128;
        __nv_bfloat16* yh = g_y_hi + gbase + (size_t)t * 128;
        __nv_bfloat16* yl = g_y_lo + gbase + (size_t)t * 128;
#pragma unroll
        for (int d4 = 0; d4 < 8; ++d4) {
            float4 v = *reinterpret_cast<const float4*>(Sout + (size_t)t * LDO + d4 * 4);
            float4 sv = *reinterpret_cast<const float4*>(sumV + d4 * 4);
            float4 g = *reinterpret_cast<const float4*>(gp + d4 * 4);
            float4 y;
            y.x = (v.x + sv.x) * inv * g.x;
            y.y = (v.y + sv.y) * inv * g.y;
            y.z = (v.z + sv.z) * inv * g.z;
            y.w = (v.w + sv.w) * inv * g.w;
            __nv_bfloat16 h0 = bhi(y.x), h1 = bhi(y.y), h2 = bhi(y.z), h3 = bhi(y.w);
            reinterpret_cast<__nv_bfloat162*>(yh + d4 * 4)[0] = {h0, h1};
            reinterpret_cast<__nv_bfloat162*>(yh + d4 * 4)[1] = {h2, h3};
            reinterpret_cast<__nv_bfloat162*>(yl + d4 * 4)[0] = {blo(y.x, h0), blo(y.y, h1)};
            reinterpret_cast<__nv_bfloat162*>(yl + d4 * 4)[1] = {blo(y.z, h2), blo(y.w, h3)};
        }
    }
}

// ============================= epi (r10 exact) =============================
#define E_LDB 72
#define E_AHI 0
#define E_ALO (128 * 136 * 2)
#define E_BHI (2 * 128 * 136 * 2)                 // 69632
#define E_BLO (E_BHI + 128 * E_LDB * 2)
#define EPI_SMEM (E_BLO + 128 * E_LDB * 2)        // 106496
#define E_STAGE E_BHI

__global__ void __launch_bounds__(256, 2) epi_wmma_kernel(
    const float* __restrict__ bo, float* __restrict__ out)
{
    extern __shared__ char smem[];
    __nv_bfloat16* sAhi = reinterpret_cast<__nv_bfloat16*>(smem + E_AHI);
    __nv_bfloat16* sAlo = reinterpret_cast<__nv_bfloat16*>(smem + E_ALO);
    __nv_bfloat16* sBhi = reinterpret_cast<__nv_bfloat16*>(smem + E_BHI);
    __nv_bfloat16* sBlo = reinterpret_cast<__nv_bfloat16*>(smem + E_BLO);
    float* stage = reinterpret_cast<float*>(smem + E_STAGE);

    const int t = threadIdx.x;
    const int wid = t >> 5;
    const int row0 = blockIdx.x * 128;

#pragma unroll
    for (int it = 0; it < 8; ++it) {
        int idx = it * 256 + t;
        int r = idx >> 4, u = idx & 15;
        size_t src = (size_t)(row0 + r) * D + u * 8;
        size_t dst = (size_t)r * 136 + u * 8;
        *reinterpret_cast<uint4*>(sAhi + dst) = *reinterpret_cast<const uint4*>(g_y_hi + src);
        *reinterpret_cast<uint4*>(sAlo + dst) = *reinterpret_cast<const uint4*>(g_y_lo + src);
    }

    const int wm = (wid & 3) * 32;
    const int wn = (wid >> 2) * 32;

    for (int c = 0; c < 2; ++c) {
        __syncthreads();
#pragma unroll
        for (int it = 0; it < 4; ++it) {
            int idx = it * 256 + t;
            int k = idx >> 3, u = idx & 7;
            size_t src = (size_t)k * 128 + c * 64 + u * 8;
            size_t dst = (size_t)k * E_LDB + u * 8;
            *reinterpret_cast<uint4*>(sBhi + dst) = *reinterpret_cast<const uint4*>(g_Wo_hi + src);
            *reinterpret_cast<uint4*>(sBlo + dst) = *reinterpret_cast<const uint4*>(g_Wo_lo + src);
        }
        __syncthreads();

        wmma::fragment<wmma::accumulator, 16, 16, 16, float> acc[2][2];
#pragma unroll
        for (int i = 0; i < 2; ++i)
#pragma unroll
            for (int j = 0; j < 2; ++j) wmma::fill_fragment(acc[i][j], 0.0f);

#pragma unroll
        for (int k8 = 0; k8 < 8; ++k8) {
            wmma::fragment<wmma::matrix_a, 16, 16, 16, __nv_bfloat16, wmma::row_major> afh[2], afl[2];
            wmma::load_matrix_sync(afh[0], sAhi + (size_t)(wm +  0) * 136 + k8 * 16, 136);
            wmma::load_matrix_sync(afh[1], sAhi + (size_t)(wm + 16) * 136 + k8 * 16, 136);
            wmma::load_matrix_sync(afl[0], sAlo + (size_t)(wm +  0) * 136 + k8 * 16, 136);
            wmma::load_matrix_sync(afl[1], sAlo + (size_t)(wm + 16) * 136 + k8 * 16, 136);
#pragma unroll
            for (int j = 0; j < 2; ++j) {
                wmma::fragment<wmma::matrix_b, 16, 16, 16, __nv_bfloat16, wmma::row_major> bfh, bfl;
                wmma::load_matrix_sync(bfh, sBhi + (size_t)(k8 * 16) * E_LDB + wn + j * 16, E_LDB);
                wmma::load_matrix_sync(bfl, sBlo + (size_t)(k8 * 16) * E_LDB + wn + j * 16, E_LDB);
                wmma::mma_sync(acc[0][j], afh[0], bfh, acc[0][j]);
                wmma::mma_sync(acc[1][j], afh[1], bfh, acc[1][j]);
                wmma::mma_sync(acc[0][j], afl[0], bfh, acc[0][j]);
                wmma::mma_sync(acc[1][j], afl[1], bfh, acc[1][j]);
                wmma::mma_sync(acc[0][j], afh[0], bfl, acc[0][j]);
                wmma::mma_sync(acc[1][j], afh[1], bfl, acc[1][j]);
            }
        }

        __syncthreads();
#pragma unroll
        for (int i = 0; i < 2; ++i)
#pragma unroll
            for (int j = 0; j < 2; ++j)
                wmma::store_matrix_sync(stage + (size_t)(wm + i * 16) * 68 + wn + j * 16,
                                        acc[i][j], 68, wmma::mem_row_major);
        __syncthreads();

#pragma unroll
        for (int it = 0; it < 8; ++it) {
            int idx = it * 256 + t;
            int r = idx >> 4, q = idx & 15;
            float4 v = *reinterpret_cast<const float4*>(stage + (size_t)r * 68 + q * 4);
            float4 b = *reinterpret_cast<const float4*>(bo + c * 64 + q * 4);
            v.x += b.x; v.y += b.y; v.z += b.z; v.w += b.w;
            *reinterpret_cast<float4*>(out + (size_t)(row0 + r) * D + c * 64 + q * 4) = v;
        }
    }
}

extern "C" void kernel_launch(void* const* d_in, const int* in_sizes, int n_in,
                              void* d_out, int out_size)
{
    const float* pair  = (const float*)d_in[0];
    const float* gamma = (const float*)d_in[1];
    const float* beta  = (const float*)d_in[2];
    const float* Wq    = (const float*)d_in[3];
    const float* Wk    = (const float*)d_in[4];
    const float* Wv    = (const float*)d_in[5];
    const float* Wb    = (const float*)d_in[6];
    const float* Wg    = (const float*)d_in[7];
    const float* bg    = (const float*)d_in[8];
    const float* Wo    = (const float*)d_in[9];
    const float* bo    = (const float*)d_in[10];
    float* out = (float*)d_out;

    cudaFuncSetAttribute(proj_wmma_kernel, cudaFuncAttributeMaxDynamicSharedMemorySize, PROJ_SMEM);
    cudaFuncSetAttribute(attn_wmma_kernel, cudaFuncAttributeMaxDynamicSharedMemorySize, ATTN_SMEM);
    cudaFuncSetAttribute(epi_wmma_kernel,  cudaFuncAttributeMaxDynamicSharedMemorySize, EPI_SMEM);

    prep_kernel<<<320, 256>>>(Wq, Wk, Wv, Wg, Wo);
    proj_wmma_kernel<<<(L * L) / 128, 256, PROJ_SMEM>>>(pair, gamma, beta, Wb, bg);
    attn_wmma_kernel<<<dim3(L, H), 256, ATTN_SMEM>>>();
    epi_wmma_kernel<<<(L * L) / 128, 256, EPI_SMEM>>>(bo, out);
}

// round 17
// speedup vs baseline: 1.5746x; 1.0282x over previous
#include <cuda_runtime.h>
#include <cuda_bf16.h>
#include <mma.h>
#include <cstdint>

using namespace nvcuda;

#define L 256
#define D 128
#define H 4
#define SCALING 0.17677669529663687f

// ---- scratch ----
__device__ __align__(16) float g_q[L * L * D];
__device__ __align__(16) float g_k[L * L * D];
__device__ __align__(16) float g_v[L * L * D];
__device__ __align__(16) float g_gate[L * L * D];
__device__ __align__(16) float g_biasH[H * L * L];            // [h][j][k]
__device__ __align__(16) __nv_bfloat16 g_y_hi[L * L * D];     // gate*att, bf16 hi
__device__ __align__(16) __nv_bfloat16 g_y_lo[L * L * D];     // bf16 lo
__device__ __align__(16) __nv_bfloat16 g_B_hi[128 * 512];     // [k][n] (Wq|Wk|Wv|Wg)
__device__ __align__(16) __nv_bfloat16 g_B_lo[128 * 512];
__device__ __align__(16) __nv_bfloat16 g_Wo_hi[128 * 128];    // [k][n]
__device__ __align__(16) __nv_bfloat16 g_Wo_lo[128 * 128];

__device__ __forceinline__ __nv_bfloat16 bhi(float x) { return __float2bfloat16_rn(x); }
__device__ __forceinline__ __nv_bfloat16 blo(float x, __nv_bfloat16 h) {
    return __float2bfloat16_rn(x - __bfloat162float(h));
}

// ---- prep ----
__global__ void __launch_bounds__(256) prep_kernel(
    const float* __restrict__ Wq, const float* __restrict__ Wk,
    const float* __restrict__ Wv, const float* __restrict__ Wg,
    const float* __restrict__ Wo)
{
    if (blockIdx.x < 256) {
        int idx = blockIdx.x * 256 + threadIdx.x;
        int k = idx >> 9;
        int n = idx & 511;
        const float* W = (n < 128) ? Wq : (n < 256) ? Wk : (n < 384) ? Wv : Wg;
        float w = W[k * 128 + (n & 127)];
        __nv_bfloat16 h = bhi(w);
        g_B_hi[idx] = h;
        g_B_lo[idx] = blo(w, h);
    } else {
        int idx = (blockIdx.x - 256) * 256 + threadIdx.x;
        float w = Wo[idx];
        __nv_bfloat16 h = bhi(w);
        g_Wo_hi[idx] = h;
        g_Wo_lo[idx] = blo(w, h);
    }
}

// ============================= proj =============================
// q/k chunks: 1-pass (Ah*Bh); gate: 2-pass (+Al*Bh); v: 3-pass (+Ah*Bl).
// B_lo staged only for v chunks.
#define LDA 136
#define LDB2 72
#define A_HI_OFF 0
#define A_LO_OFF (128 * LDA * 2)
#define B_HI_OFF (2 * 128 * LDA * 2)              // 69632
#define B_LO_OFF (B_HI_OFF + 128 * LDB2 * 2)
#define PROJ_SMEM (B_LO_OFF + 128 * LDB2 * 2)     // 106496
#define STAGE_OFF B_HI_OFF                         // fp32 [128][68]

__global__ void __launch_bounds__(256, 2) proj_wmma_kernel(
    const float* __restrict__ pair,
    const float* __restrict__ gamma, const float* __restrict__ beta,
    const float* __restrict__ Wb, const float* __restrict__ bg)
{
    extern __shared__ char smem[];
    __nv_bfloat16* sAhi = reinterpret_cast<__nv_bfloat16*>(smem + A_HI_OFF);
    __nv_bfloat16* sAlo = reinterpret_cast<__nv_bfloat16*>(smem + A_LO_OFF);
    __nv_bfloat16* sBhi = reinterpret_cast<__nv_bfloat16*>(smem + B_HI_OFF);
    __nv_bfloat16* sBlo = reinterpret_cast<__nv_bfloat16*>(smem + B_LO_OFF);
    float* stage = reinterpret_cast<float*>(smem + STAGE_OFF);

    const int t = threadIdx.x;
    const int wid = t >> 5, lane = t & 31;
    const int row0 = blockIdx.x * 128;

    float4 gv = reinterpret_cast<const float4*>(gamma)[lane];
    float4 bv = reinterpret_cast<const float4*>(beta)[lane];
    float4 wbr[4];
#pragma unroll
    for (int i = 0; i < 4; ++i)
        wbr[i] = *reinterpret_cast<const float4*>(Wb + (lane * 4 + i) * 4);

#pragma unroll 2
    for (int rr = 0; rr < 16; ++rr) {
        int r = wid * 16 + rr;
        float4 x = reinterpret_cast<const float4*>(pair + (size_t)(row0 + r) * D)[lane];
        float s  = x.x + x.y + x.z + x.w;
        float s2 = x.x * x.x + x.y * x.y + x.z * x.z + x.w * x.w;
#pragma unroll
        for (int o = 16; o > 0; o >>= 1) {
            s  += __shfl_xor_sync(0xffffffffu, s,  o);
            s2 += __shfl_xor_sync(0xffffffffu, s2, o);
        }
        float mu  = s * (1.0f / 128.0f);
        float var = s2 * (1.0f / 128.0f) - mu * mu;
        float rs  = rsqrtf(var + 1e-5f);
        float4 xn;
        xn.x = (x.x - mu) * rs * gv.x + bv.x;
        xn.y = (x.y - mu) * rs * gv.y + bv.y;
        xn.z = (x.z - mu) * rs * gv.z + bv.z;
        xn.w = (x.w - mu) * rs * gv.w + bv.w;

        __nv_bfloat16 h0 = bhi(xn.x), h1 = bhi(xn.y), h2 = bhi(xn.z), h3 = bhi(xn.w);
        size_t aoff = (size_t)r * LDA + lane * 4;
        reinterpret_cast<__nv_bfloat162*>(sAhi + aoff)[0] = {h0, h1};
        reinterpret_cast<__nv_bfloat162*>(sAhi + aoff)[1] = {h2, h3};
        reinterpret_cast<__nv_bfloat162*>(sAlo + aoff)[0] = {blo(xn.x, h0), blo(xn.y, h1)};
        reinterpret_cast<__nv_bfloat162*>(sAlo + aoff)[1] = {blo(xn.z, h2), blo(xn.w, h3)};

        float4 bacc;
        bacc.x = xn.x * wbr[0].x + xn.y * wbr[1].x + xn.z * wbr[2].x + xn.w * wbr[3].x;
        bacc.y = xn.x * wbr[0].y + xn.y * wbr[1].y + xn.z * wbr[2].y + xn.w * wbr[3].y;
        bacc.z = xn.x * wbr[0].z + xn.y * wbr[1].z + xn.z * wbr[2].z + xn.w * wbr[3].z;
        bacc.w = xn.x * wbr[0].w + xn.y * wbr[1].w + xn.z * wbr[2].w + xn.w * wbr[3].w;
#pragma unroll
        for (int o = 16; o > 0; o >>= 1) {
            bacc.x += __shfl_xor_sync(0xffffffffu, bacc.x, o);
            bacc.y += __shfl_xor_sync(0xffffffffu, bacc.y, o);
            bacc.z += __shfl_xor_sync(0xffffffffu, bacc.z, o);
            bacc.w += __shfl_xor_sync(0xffffffffu, bacc.w, o);
        }
        if (lane == 0) {
            int p = row0 + r;
            g_biasH[0 * 65536 + p] = bacc.x;
            g_biasH[1 * 65536 + p] = bacc.y;
            g_biasH[2 * 65536 + p] = bacc.z;
            g_biasH[3 * 65536 + p] = bacc.w;
        }
    }

    const int wm = (wid & 3) * 32;
    const int wn = (wid >> 2) * 32;

    for (int c = 0; c < 8; ++c) {
        const bool useAl = (c >= 4);             // gate & v apply the x_lo correction
        const bool useBl = (c == 4 || c == 5);   // only v applies the W_lo correction
        __syncthreads();               // prior chunk's B/stage reads done
#pragma unroll
        for (int it = 0; it < 4; ++it) {
            int idx = it * 256 + t;
            int k = idx >> 3, u = idx & 7;
            size_t src = (size_t)k * 512 + c * 64 + u * 8;
            size_t dst = (size_t)k * LDB2 + u * 8;
            *reinterpret_cast<uint4*>(sBhi + dst) = *reinterpret_cast<const uint4*>(g_B_hi + src);
            if (useBl)
                *reinterpret_cast<uint4*>(sBlo + dst) = *reinterpret_cast<const uint4*>(g_B_lo + src);
        }
        __syncthreads();

        wmma::fragment<wmma::accumulator, 16, 16, 16, float> acc[2][2];
#pragma unroll
        for (int i = 0; i < 2; ++i)
#pragma unroll
            for (int j = 0; j < 2; ++j) wmma::fill_fragment(acc[i][j], 0.0f);

#pragma unroll
        for (int k8 = 0; k8 < 8; ++k8) {
            wmma::fragment<wmma::matrix_a, 16, 16, 16, __nv_bfloat16, wmma::row_major> afh[2], afl[2];
            wmma::load_matrix_sync(afh[0], sAhi + (size_t)(wm +  0) * LDA + k8 * 16, LDA);
            wmma::load_matrix_sync(afh[1], sAhi + (size_t)(wm + 16) * LDA + k8 * 16, LDA);
            if (useAl) {
                wmma::load_matrix_sync(afl[0], sAlo + (size_t)(wm +  0) * LDA + k8 * 16, LDA);
                wmma::load_matrix_sync(afl[1], sAlo + (size_t)(wm + 16) * LDA + k8 * 16, LDA);
            }
#pragma unroll
            for (int j = 0; j < 2; ++j) {
                wmma::fragment<wmma::matrix_b, 16, 16, 16, __nv_bfloat16, wmma::row_major> bfh;
                wmma::load_matrix_sync(bfh, sBhi + (size_t)(k8 * 16) * LDB2 + wn + j * 16, LDB2);
                wmma::mma_sync(acc[0][j], afh[0], bfh, acc[0][j]);
                wmma::mma_sync(acc[1][j], afh[1], bfh, acc[1][j]);
                if (useAl) {
                    wmma::mma_sync(acc[0][j], afl[0], bfh, acc[0][j]);
                    wmma::mma_sync(acc[1][j], afl[1], bfh, acc[1][j]);
                }
                if (useBl) {
                    wmma::fragment<wmma::matrix_b, 16, 16, 16, __nv_bfloat16, wmma::row_major> bfl;
                    wmma::load_matrix_sync(bfl, sBlo + (size_t)(k8 * 16) * LDB2 + wn + j * 16, LDB2);
                    wmma::mma_sync(acc[0][j], afh[0], bfl, acc[0][j]);
                    wmma::mma_sync(acc[1][j], afh[1], bfl, acc[1][j]);
                }
            }
        }

        if (c < 6) {
            float* dst = (c < 2) ? g_q : (c < 4) ? g_k : g_v;
            int coloff = (c & 1) * 64;
            if (c < 2) {
#pragma unroll
                for (int i = 0; i < 2; ++i)
#pragma unroll
                    for (int j = 0; j < 2; ++j)
#pragma unroll
                        for (int e = 0; e < acc[i][j].num_elements; ++e)
                            acc[i][j].x[e] *= SCALING;
            }
#pragma unroll
            for (int i = 0; i < 2; ++i)
#pragma unroll
                for (int j = 0; j < 2; ++j)
                    wmma::store_matrix_sync(
                        dst + (size_t)(row0 + wm + i * 16) * D + coloff + wn + j * 16,
                        acc[i][j], D, wmma::mem_row_major);
        } else {
            int coloff = (c - 6) * 64;
            __syncthreads();
#pragma unroll
            for (int i = 0; i < 2; ++i)
#pragma unroll
                for (int j = 0; j < 2; ++j)
                    wmma::store_matrix_sync(
                        stage + (size_t)(wm + i * 16) * 68 + wn + j * 16,
                        acc[i][j], 68, wmma::mem_row_major);
            __syncthreads();
#pragma unroll
            for (int it = 0; it < 8; ++it) {
                int idx = it * 256 + t;
                int r = idx >> 4, q = idx & 15;
                float4 v = *reinterpret_cast<const float4*>(stage + (size_t)r * 68 + q * 4);
                float4 bgv = *reinterpret_cast<const float4*>(bg + coloff + q * 4);
                float4 o;
                o.x = 1.0f / (1.0f + __expf(-(v.x + bgv.x)));
                o.y = 1.0f / (1.0f + __expf(-(v.y + bgv.y)));
                o.z = 1.0f / (1.0f + __expf(-(v.z + bgv.z)));
                o.w = 1.0f / (1.0f + __expf(-(v.w + bgv.w)));
                *reinterpret_cast<float4*>(g_gate + (size_t)(row0 + r) * D + coloff + q * 4) = o;
            }
        }
    }
}

// ============================= attn (r16 exact) =============================
// Centered-P: out = sumV + P' V (P' = exp(s)-1, single bf16).
#define LDQ 40
#define LDSS 260
#define LDP2 264
#define LDO 36
#define AQH 0
#define AKB 20480
#define AVH 40960
#define AVL 61440
#define AST 81920
#define APH 98560
#define APV 107008
#define ATTN_SMEM 108288

__global__ void __launch_bounds__(256, 2) attn_wmma_kernel()
{
    extern __shared__ char smem[];
    __nv_bfloat16* Qh  = reinterpret_cast<__nv_bfloat16*>(smem + AQH);
    __nv_bfloat16* Kb  = reinterpret_cast<__nv_bfloat16*>(smem + AKB);
    __nv_bfloat16* Vh  = reinterpret_cast<__nv_bfloat16*>(smem + AVH);
    __nv_bfloat16* Vl  = reinterpret_cast<__nv_bfloat16*>(smem + AVL);
    float*         St  = reinterpret_cast<float*>(smem + AST);
    __nv_bfloat16* Pth = reinterpret_cast<__nv_bfloat16*>(smem + APH);
    float*     partial = reinterpret_cast<float*>(smem + APV);
    float*        sumV = reinterpret_cast<float*>(smem + APV + 1024);
    float*       Sout  = reinterpret_cast<float*>(smem + 0);

    const int i = blockIdx.x;
    const int h = blockIdx.y;
    const int t = threadIdx.x;
    const int w = t >> 5;
    const size_t gbase = (size_t)i * 256 * 128 + h * 32;

#pragma unroll
    for (int u = 0; u < 8; ++u) {
        int idx = u * 256 + t;
        int row = idx >> 3, c4 = idx & 7;
        size_t goff = gbase + (size_t)row * 128 + c4 * 4;
        size_t soff = (size_t)row * LDQ + c4 * 4;
        float4 q4 = *reinterpret_cast<const float4*>(g_q + goff);
        float4 k4 = *reinterpret_cast<const float4*>(g_k + goff);
        float4 v4 = *reinterpret_cast<const float4*>(g_v + goff);
        reinterpret_cast<__nv_bfloat162*>(Qh + soff)[0] = {bhi(q4.x), bhi(q4.y)};
        reinterpret_cast<__nv_bfloat162*>(Qh + soff)[1] = {bhi(q4.z), bhi(q4.w)};
        reinterpret_cast<__nv_bfloat162*>(Kb + soff)[0] = {bhi(k4.x), bhi(k4.y)};
        reinterpret_cast<__nv_bfloat162*>(Kb + soff)[1] = {bhi(k4.z), bhi(k4.w)};
        __nv_bfloat16 vh0 = bhi(v4.x), vh1 = bhi(v4.y), vh2 = bhi(v4.z), vh3 = bhi(v4.w);
        reinterpret_cast<__nv_bfloat162*>(Vh + soff)[0] = {vh0, vh1};
        reinterpret_cast<__nv_bfloat162*>(Vh + soff)[1] = {vh2, vh3};
        reinterpret_cast<__nv_bfloat162*>(Vl + soff)[0] = {blo(v4.x, vh0), blo(v4.y, vh1)};
        reinterpret_cast<__nv_bfloat162*>(Vl + soff)[1] = {blo(v4.z, vh2), blo(v4.w, vh3)};
    }

    {
        int lane = t & 31;
        float acc = 0.0f;
        const float* vp = g_v + gbase + (size_t)(w * 32) * 128 + lane;
#pragma unroll 8
        for (int kk = 0; kk < 32; ++kk) acc += vp[(size_t)kk * 128];
        partial[w * 32 + lane] = acc;
    }
    __syncthreads();
    if (t < 32) {
        float s = 0.0f;
#pragma unroll
        for (int w2 = 0; w2 < 8; ++w2) s += partial[w2 * 32 + t];
        sumV[t] = s;
    }
    __syncthreads();

    const float* biasp = g_biasH + (size_t)h * 65536;
    const int j0w = w * 32;

    wmma::fragment<wmma::accumulator, 16, 16, 16, float> acc_o[2][2];
#pragma unroll
    for (int a = 0; a < 2; ++a)
#pragma unroll
        for (int b = 0; b < 2; ++b) wmma::fill_fragment(acc_o[a][b], 0.0f);
    float ssum = 0.0f;

    for (int c = 0; c < 16; ++c) {
        const int k0c = c * 16;

        wmma::fragment<wmma::accumulator, 16, 16, 16, float> accs[2];
#pragma unroll
        for (int a = 0; a < 2; ++a)
            wmma::load_matrix_sync(accs[a],
                biasp + (size_t)(j0w + a * 16) * 256 + k0c, 256, wmma::mem_row_major);
#pragma unroll
        for (int s = 0; s < 2; ++s) {
            wmma::fragment<wmma::matrix_b, 16, 16, 16, __nv_bfloat16, wmma::col_major> kf;
            wmma::load_matrix_sync(kf, Kb + (size_t)k0c * LDQ + s * 16, LDQ);
            wmma::fragment<wmma::matrix_a, 16, 16, 16, __nv_bfloat16, wmma::row_major> af[2];
            wmma::load_matrix_sync(af[0], Qh + (size_t)(j0w +  0) * LDQ + s * 16, LDQ);
            wmma::load_matrix_sync(af[1], Qh + (size_t)(j0w + 16) * LDQ + s * 16, LDQ);
            wmma::mma_sync(accs[0], af[0], kf, accs[0]);
            wmma::mma_sync(accs[1], af[1], kf, accs[1]);
        }
#pragma unroll
        for (int a = 0; a < 2; ++a)
            wmma::store_matrix_sync(St + j0w + a * 16, accs[a], LDSS, wmma::mem_col_major);
        __syncwarp();

        {
            float acc = 0.0f;
#pragma unroll 4
            for (int kk = 0; kk < 16; ++kk) {
                float p = __expf(St[(size_t)kk * LDSS + t]);
                acc += p;
                Pth[(size_t)kk * LDP2 + t] = bhi(p - 1.0f);
            }
            ssum += acc;
        }
        __syncwarp();

        wmma::fragment<wmma::matrix_a, 16, 16, 16, __nv_bfloat16, wmma::col_major> aph[2];
#pragma unroll
        for (int a = 0; a < 2; ++a)
            wmma::load_matrix_sync(aph[a], Pth + j0w + a * 16, LDP2);
#pragma unroll
        for (int b = 0; b < 2; ++b) {
            wmma::fragment<wmma::matrix_b, 16, 16, 16, __nv_bfloat16, wmma::row_major> vfh, vfl;
            wmma::load_matrix_sync(vfh, Vh + (size_t)k0c * LDQ + b * 16, LDQ);
            wmma::load_matrix_sync(vfl, Vl + (size_t)k0c * LDQ + b * 16, LDQ);
#pragma unroll
            for (int a = 0; a < 2; ++a) {
                wmma::mma_sync(acc_o[a][b], aph[a], vfh, acc_o[a][b]);
                wmma::mma_sync(acc_o[a][b], aph[a], vfl, acc_o[a][b]);
            }
        }
    }

    __syncthreads();
#pragma unroll
    for (int a = 0; a < 2; ++a)
#pragma unroll
        for (int b = 0; b < 2; ++b)
            wmma::store_matrix_sync(Sout + (size_t)(j0w + a * 16) * LDO + b * 16,
                                    acc_o[a][b], LDO, wmma::mem_row_major);
    __syncwarp();

    {
        float inv = 1.0f / ssum;
        const float* gp = g_gate + gbase + (size_t)t * 128;
        __nv_bfloat16* yh = g_y_hi + gbase + (size_t)t * 128;
        __nv_bfloat16* yl = g_y_lo + gbase + (size_t)t * 128;
#pragma unroll
        for (int d4 = 0; d4 < 8; ++d4) {
            float4 v = *reinterpret_cast<const float4*>(Sout + (size_t)t * LDO + d4 * 4);
            float4 sv = *reinterpret_cast<const float4*>(sumV + d4 * 4);
            float4 g = *reinterpret_cast<const float4*>(gp + d4 * 4);
            float4 y;
            y.x = (v.x + sv.x) * inv * g.x;
            y.y = (v.y + sv.y) * inv * g.y;
            y.z = (v.z + sv.z) * inv * g.z;
            y.w = (v.w + sv.w) * inv * g.w;
            __nv_bfloat16 h0 = bhi(y.x), h1 = bhi(y.y), h2 = bhi(y.z), h3 = bhi(y.w);
            reinterpret_cast<__nv_bfloat162*>(yh + d4 * 4)[0] = {h0, h1};
            reinterpret_cast<__nv_bfloat162*>(yh + d4 * 4)[1] = {h2, h3};
            reinterpret_cast<__nv_bfloat162*>(yl + d4 * 4)[0] = {blo(y.x, h0), blo(y.y, h1)};
            reinterpret_cast<__nv_bfloat162*>(yl + d4 * 4)[1] = {blo(y.z, h2), blo(y.w, h3)};
        }
    }
}

// ============================= epi (r10 exact) =============================
#define E_LDB 72
#define E_AHI 0
#define E_ALO (128 * 136 * 2)
#define E_BHI (2 * 128 * 136 * 2)                 // 69632
#define E_BLO (E_BHI + 128 * E_LDB * 2)
#define EPI_SMEM (E_BLO + 128 * E_LDB * 2)        // 106496
#define E_STAGE E_BHI

__global__ void __launch_bounds__(256, 2) epi_wmma_kernel(
    const float* __restrict__ bo, float* __restrict__ out)
{
    extern __shared__ char smem[];
    __nv_bfloat16* sAhi = reinterpret_cast<__nv_bfloat16*>(smem + E_AHI);
    __nv_bfloat16* sAlo = reinterpret_cast<__nv_bfloat16*>(smem + E_ALO);
    __nv_bfloat16* sBhi = reinterpret_cast<__nv_bfloat16*>(smem + E_BHI);
    __nv_bfloat16* sBlo = reinterpret_cast<__nv_bfloat16*>(smem + E_BLO);
    float* stage = reinterpret_cast<float*>(smem + E_STAGE);

    const int t = threadIdx.x;
    const int wid = t >> 5;
    const int row0 = blockIdx.x * 128;

#pragma unroll
    for (int it = 0; it < 8; ++it) {
        int idx = it * 256 + t;
        int r = idx >> 4, u = idx & 15;
        size_t src = (size_t)(row0 + r) * D + u * 8;
        size_t dst = (size_t)r * 136 + u * 8;
        *reinterpret_cast<uint4*>(sAhi + dst) = *reinterpret_cast<const uint4*>(g_y_hi + src);
        *reinterpret_cast<uint4*>(sAlo + dst) = *reinterpret_cast<const uint4*>(g_y_lo + src);
    }

    const int wm = (wid & 3) * 32;
    const int wn = (wid >> 2) * 32;

    for (int c = 0; c < 2; ++c) {
        __syncthreads();
#pragma unroll
        for (int it = 0; it < 4; ++it) {
            int idx = it * 256 + t;
            int k = idx >> 3, u = idx & 7;
            size_t src = (size_t)k * 128 + c * 64 + u * 8;
            size_t dst = (size_t)k * E_LDB + u * 8;
            *reinterpret_cast<uint4*>(sBhi + dst) = *reinterpret_cast<const uint4*>(g_Wo_hi + src);
            *reinterpret_cast<uint4*>(sBlo + dst) = *reinterpret_cast<const uint4*>(g_Wo_lo + src);
        }
        __syncthreads();

        wmma::fragment<wmma::accumulator, 16, 16, 16, float> acc[2][2];
#pragma unroll
        for (int i = 0; i < 2; ++i)
#pragma unroll
            for (int j = 0; j < 2; ++j) wmma::fill_fragment(acc[i][j], 0.0f);

#pragma unroll
        for (int k8 = 0; k8 < 8; ++k8) {
            wmma::fragment<wmma::matrix_a, 16, 16, 16, __nv_bfloat16, wmma::row_major> afh[2], afl[2];
            wmma::load_matrix_sync(afh[0], sAhi + (size_t)(wm +  0) * 136 + k8 * 16, 136);
            wmma::load_matrix_sync(afh[1], sAhi + (size_t)(wm + 16) * 136 + k8 * 16, 136);
            wmma::load_matrix_sync(afl[0], sAlo + (size_t)(wm +  0) * 136 + k8 * 16, 136);
            wmma::load_matrix_sync(afl[1], sAlo + (size_t)(wm + 16) * 136 + k8 * 16, 136);
#pragma unroll
            for (int j = 0; j < 2; ++j) {
                wmma::fragment<wmma::matrix_b, 16, 16, 16, __nv_bfloat16, wmma::row_major> bfh, bfl;
                wmma::load_matrix_sync(bfh, sBhi + (size_t)(k8 * 16) * E_LDB + wn + j * 16, E_LDB);
                wmma::load_matrix_sync(bfl, sBlo + (size_t)(k8 * 16) * E_LDB + wn + j * 16, E_LDB);
                wmma::mma_sync(acc[0][j], afh[0], bfh, acc[0][j]);
                wmma::mma_sync(acc[1][j], afh[1], bfh, acc[1][j]);
                wmma::mma_sync(acc[0][j], afl[0], bfh, acc[0][j]);
                wmma::mma_sync(acc[1][j], afl[1], bfh, acc[1][j]);
                wmma::mma_sync(acc[0][j], afh[0], bfl, acc[0][j]);
                wmma::mma_sync(acc[1][j], afh[1], bfl, acc[1][j]);
            }
        }

        __syncthreads();
#pragma unroll
        for (int i = 0; i < 2; ++i)
#pragma unroll
            for (int j = 0; j < 2; ++j)
                wmma::store_matrix_sync(stage + (size_t)(wm + i * 16) * 68 + wn + j * 16,
                                        acc[i][j], 68, wmma::mem_row_major);
        __syncthreads();

#pragma unroll
        for (int it = 0; it < 8; ++it) {
            int idx = it * 256 + t;
            int r = idx >> 4, q = idx & 15;
            float4 v = *reinterpret_cast<const float4*>(stage + (size_t)r * 68 + q * 4);
            float4 b = *reinterpret_cast<const float4*>(bo + c * 64 + q * 4);
            v.x += b.x; v.y += b.y; v.z += b.z; v.w += b.w;
            *reinterpret_cast<float4*>(out + (size_t)(row0 + r) * D + c * 64 + q * 4) = v;
        }
    }
}

extern "C" void kernel_launch(void* const* d_in, const int* in_sizes, int n_in,
                              void* d_out, int out_size)
{
    const float* pair  = (const float*)d_in[0];
    const float* gamma = (const float*)d_in[1];
    const float* beta  = (const float*)d_in[2];
    const float* Wq    = (const float*)d_in[3];
    const float* Wk    = (const float*)d_in[4];
    const float* Wv    = (const float*)d_in[5];
    const float* Wb    = (const float*)d_in[6];
    const float* Wg    = (const float*)d_in[7];
    const float* bg    = (const float*)d_in[8];
    const float* Wo    = (const float*)d_in[9];
    const float* bo    = (const float*)d_in[10];
    float* out = (float*)d_out;

    cudaFuncSetAttribute(proj_wmma_kernel, cudaFuncAttributeMaxDynamicSharedMemorySize, PROJ_SMEM);
    cudaFuncSetAttribute(attn_wmma_kernel, cudaFuncAttributeMaxDynamicSharedMemorySize, ATTN_SMEM);
    cudaFuncSetAttribute(epi_wmma_kernel,  cudaFuncAttributeMaxDynamicSharedMemorySize, EPI_SMEM);

    prep_kernel<<<320, 256>>>(Wq, Wk, Wv, Wg, Wo);
    proj_wmma_kernel<<<(L * L) / 128, 256, PROJ_SMEM>>>(pair, gamma, beta, Wb, bg);
    attn_wmma_kernel<<<dim3(L, H), 256, ATTN_SMEM>>>();
    epi_wmma_kernel<<<(L * L) / 128, 256, EPI_SMEM>>>(bo, out);
}